// round 13
// baseline (speedup 1.0000x reference)
#include <cuda_runtime.h>
#include <cuda_fp16.h>
#include <math.h>
#include <stdint.h>

#define NPTS        131072
#define NBATCH      64
#define FEAT_DIM    32
#define TOKEN_DIM   768
#define MAX_TOKENS  128
#define SORT_N      4096
#define CPB         144
#define CTOT        (NBATCH * CPB)            // 9216
#define TOK_ELEMS   (NBATCH * MAX_TOKENS * TOKEN_DIM)
#define CENT_ELEMS  (NBATCH * MAX_TOKENS * 4)

// ---------------- Scratch arenas ----------------
#define HOFF_H0 0ULL
#define HOFF_H1 16777216ULL
#define HOFF_H2 50331648ULL
#define HOFF_H3 117440512ULL
#define HOFF_PF 218103808ULL
#define ACTH_TOT 318767104ULL
__device__ __half d_acth[ACTH_TOT];

#define WOFF_1 0ULL
#define WOFF_2 32768ULL
#define WOFF_3 163840ULL
#define WOFF_4 557056ULL
#define WOFF_5 1146880ULL
#define WTH_TOT 1441792ULL
__device__ __half d_wth[WTH_TOT];

__device__ float d_h0f[(size_t)NPTS * 96];

// pass-2 fp32 candidate chain (validated path, 128x128 tiles)
__device__ float d_c0 [(size_t)CTOT * 96];
__device__ float d_c1 [(size_t)CTOT * 256];
__device__ float d_c2 [(size_t)CTOT * 512];
__device__ float d_c3 [(size_t)CTOT * 768];
__device__ float d_cpf[(size_t)CTOT * 768];
__device__ float d_cg [(size_t)CTOT * 384];

__device__ float d_scores[NPTS];
__device__ float d_cscore[CTOT];
__device__ int   d_off[NBATCH + 1];
__device__ int   d_cand[CTOT];
__device__ int   d_fsel_j[NBATCH * MAX_TOKENS];
__device__ int   d_fsel_p[NBATCH * MAX_TOKENS];

// ---------------- PTX helpers ----------------
__device__ __forceinline__ uint32_t smem_u32(const void* p) {
    uint32_t a;
    asm("{ .reg .u64 t; cvta.to.shared.u64 t, %1; cvt.u32.u64 %0, t; }" : "=r"(a) : "l"(p));
    return a;
}
#define CP_ASYNC16(dst, src) \
    asm volatile("cp.async.cg.shared.global [%0], [%1], 16;" :: "r"(dst), "l"(src))
#define CP_COMMIT() asm volatile("cp.async.commit_group;")
#define CP_WAIT(n)  asm volatile("cp.async.wait_group %0;" :: "n"(n))
#define LDMATRIX_X4(r0, r1, r2, r3, addr) \
    asm volatile("ldmatrix.sync.aligned.m8n8.x4.shared.b16 {%0,%1,%2,%3}, [%4];" \
        : "=r"(r0), "=r"(r1), "=r"(r2), "=r"(r3) : "r"(addr))
#define MMA16816(d, a, b) \
    asm volatile("mma.sync.aligned.m16n8k16.row.col.f32.f16.f16.f32 " \
        "{%0,%1,%2,%3}, {%4,%5,%6,%7}, {%8,%9}, {%0,%1,%2,%3};" \
        : "+f"((d)[0]), "+f"((d)[1]), "+f"((d)[2]), "+f"((d)[3]) \
        : "r"((a)[0]), "r"((a)[1]), "r"((a)[2]), "r"((a)[3]), \
          "r"((b)[0]), "r"((b)[1]))

// ---------------- fused weight convert: all 5 matrices in one launch ---------
// For each: W[K,Nn] fp32 -> [Nn,Kpad] fp16 (transposed, K padded)
__global__ void wsplit_all(const float* __restrict__ W1, const float* __restrict__ W2,
                           const float* __restrict__ W3, const float* __restrict__ W4,
                           const float* __restrict__ W5)
{
    int idx = blockIdx.x * blockDim.x + threadIdx.x;
    const float* W; __half* t; int K, Kpad, Nn;
    if (idx < 32768)        { W = W1; t = d_wth + WOFF_1; K =  96; Kpad = 128; Nn = 256; }
    else if (idx < 163840)  { W = W2; t = d_wth + WOFF_2; K = 256; Kpad = 256; Nn = 512; idx -= 32768; }
    else if (idx < 557056)  { W = W3; t = d_wth + WOFF_3; K = 512; Kpad = 512; Nn = 768; idx -= 163840; }
    else if (idx < 1146880) { W = W4; t = d_wth + WOFF_4; K = 768; Kpad = 768; Nn = 768; idx -= 557056; }
    else if (idx < 1441792) { W = W5; t = d_wth + WOFF_5; K = 768; Kpad = 768; Nn = 384; idx -= 1146880; }
    else return;
    int n = idx / Kpad, k = idx - n * Kpad;
    t[idx] = __float2half((k < K) ? W[(size_t)k * Nn + n] : 0.0f);
}

// ---------------- Stage A (+ zero scores fused) ----------------
__global__ __launch_bounds__(128) void stage_a_kernel(
    const float* __restrict__ coords, const float* __restrict__ features,
    const float* __restrict__ times,
    const float* __restrict__ ln_g, const float* __restrict__ ln_b,
    const float* __restrict__ sw1, const float* __restrict__ sb1,
    const float* __restrict__ sw2, const float* __restrict__ sb2)
{
    __shared__ float s1[256], s2[4096], sb1s[64], sb2s[64], lg[4], lb[4];
    for (int t = threadIdx.x; t < 256; t += 128)  s1[t] = sw1[t];
    for (int t = threadIdx.x; t < 4096; t += 128) s2[t] = sw2[t];
    if (threadIdx.x < 64) { sb1s[threadIdx.x] = sb1[threadIdx.x]; sb2s[threadIdx.x] = sb2[threadIdx.x]; }
    if (threadIdx.x < 4)  { lg[threadIdx.x] = ln_g[threadIdx.x]; lb[threadIdx.x] = ln_b[threadIdx.x]; }
    __syncthreads();

    int i = blockIdx.x * 128 + threadIdx.x;
    d_scores[i] = 0.0f;                      // fused zero-init (before hgemm<2> atomics)

    float x0 = coords[i * 3 + 0], x1 = coords[i * 3 + 1], x2 = coords[i * 3 + 2], x3 = times[i];
    float mu = 0.25f * (x0 + x1 + x2 + x3);
    float e0 = x0 - mu, e1 = x1 - mu, e2 = x2 - mu, e3 = x3 - mu;
    float inv = 1.0f / sqrtf(0.25f * (e0*e0 + e1*e1 + e2*e2 + e3*e3) + 1e-5f);
    float xn0 = e0*inv*lg[0]+lb[0], xn1 = e1*inv*lg[1]+lb[1];
    float xn2 = e2*inv*lg[2]+lb[2], xn3 = e3*inv*lg[3]+lb[3];

    float t1[64];
#pragma unroll
    for (int j = 0; j < 64; j++) {
        float a = sb1s[j] + xn0*s1[j] + xn1*s1[64+j] + xn2*s1[128+j] + xn3*s1[192+j];
        t1[j] = fmaxf(a, 0.0f);
    }

    float*  hf = d_h0f + (size_t)i * 96;
    __half* hh = d_acth + HOFF_H0 + (size_t)i * 128;

#pragma unroll
    for (int c = 0; c < FEAT_DIM; c++) {
        float v = features[(size_t)i * FEAT_DIM + c];
        hf[c] = v; hh[c] = __float2half(v);
    }
    for (int j = 0; j < 64; j++) {
        float a = sb2s[j];
#pragma unroll
        for (int kk = 0; kk < 64; kk++) a += t1[kk] * s2[kk * 64 + j];
        a = fmaxf(a, 0.0f);
        hf[32 + j] = a; hh[32 + j] = __float2half(a);
    }
    __half z = __float2half(0.0f);
#pragma unroll
    for (int c = 96; c < 128; c++) hh[c] = z;
}

// ---------------- pass-1 fp16 HGEMM (4 warps, 64x64 warp tiles) --------------
#define STAGES      4
#define STAGE_BYTES 16384
#define HG_SMEM     (STAGES * STAGE_BYTES)

// MODE: 0 = relu -> fp16 C; 1 = identity -> fp16 C; 2 = relu+score (no C write)
template <int MODE>
__global__ __launch_bounds__(128) void hgemm(
    const __half* __restrict__ A, const __half* __restrict__ B,
    const float* __restrict__ bias, __half* __restrict__ C,
    const float* __restrict__ hw2,
    int K, int Nn)
{
    extern __shared__ char smraw[];
    const uint32_t sb = smem_u32(smraw);
    const int tid = threadIdx.x;
    const int lane = tid & 31, wid = tid >> 5;
    const int wm = wid & 1, wn = wid >> 1;
    const int bm = blockIdx.y << 7, bn = blockIdx.x << 7;
    const int nIters = K >> 5;

    float acc[4][8][4];
#pragma unroll
    for (int a = 0; a < 4; a++)
#pragma unroll
        for (int b = 0; b < 8; b++)
#pragma unroll
            for (int c = 0; c < 4; c++) acc[a][b][c] = 0.0f;

    auto load_stage = [&](int s) {
        uint32_t base = sb + (uint32_t)(s % STAGES) * STAGE_BYTES;
        int k0 = s << 5;
#pragma unroll
        for (int t = 0; t < 8; t++) {
            int q = tid + (t << 7);
            int sec = q >> 9;
            int idx = q & 511;
            int row = idx >> 2;
            int c = idx & 3;
            uint32_t dst = base + (sec << 13) + row * 64 + ((c ^ ((row >> 1) & 3)) << 4);
            const __half* gp = (sec == 0)
                ? A + (size_t)(bm + row) * K + k0 + (c << 3)
                : B + (size_t)(bn + row) * K + k0 + (c << 3);
            CP_ASYNC16(dst, gp);
        }
    };

#pragma unroll
    for (int s = 0; s < STAGES - 1; s++) {
        if (s < nIters) load_stage(s);
        CP_COMMIT();
    }

    for (int it = 0; it < nIters; it++) {
        CP_WAIT(STAGES - 2);
        __syncthreads();
        int nx = it + STAGES - 1;
        if (nx < nIters) load_stage(nx);
        CP_COMMIT();

        uint32_t base = sb + (uint32_t)(it % STAGES) * STAGE_BYTES;
#pragma unroll
        for (int k16 = 0; k16 < 2; k16++) {
            uint32_t af[4][4];
#pragma unroll
            for (int mt = 0; mt < 4; mt++) {
                int row = (wm << 6) + (mt << 4) + (lane & 15);
                int ch = (k16 << 1) + (lane >> 4);
                uint32_t ad = base + row * 64 + ((ch ^ ((row >> 1) & 3)) << 4);
                LDMATRIX_X4(af[mt][0], af[mt][1], af[mt][2], af[mt][3], ad);
            }
            uint32_t bfr[8][2];
#pragma unroll
            for (int pair = 0; pair < 4; pair++) {
                int row = (wn << 6) + (pair << 4) + (((lane >> 4) & 1) << 3) + (lane & 7);
                int ch = (k16 << 1) + ((lane >> 3) & 1);
                uint32_t ad = base + 8192 + row * 64 + ((ch ^ ((row >> 1) & 3)) << 4);
                uint32_t r0, r1, r2, r3;
                LDMATRIX_X4(r0, r1, r2, r3, ad);
                bfr[pair * 2][0] = r0;      bfr[pair * 2][1] = r1;
                bfr[pair * 2 + 1][0] = r2;  bfr[pair * 2 + 1][1] = r3;
            }
#pragma unroll
            for (int mt = 0; mt < 4; mt++)
#pragma unroll
                for (int nt = 0; nt < 8; nt++)
                    MMA16816(acc[mt][nt], af[mt], bfr[nt]);
        }
    }

    if (MODE == 2) {
#pragma unroll
        for (int mt = 0; mt < 4; mt++)
#pragma unroll
            for (int h = 0; h < 2; h++) {
                float s = 0.0f;
#pragma unroll
                for (int nt = 0; nt < 8; nt++) {
                    int c0 = bn + (wn << 6) + (nt << 3) + ((lane & 3) << 1);
                    float v0 = fmaxf(acc[mt][nt][h * 2 + 0] + bias[c0], 0.0f);
                    float v1 = fmaxf(acc[mt][nt][h * 2 + 1] + bias[c0 + 1], 0.0f);
                    s += v0 * hw2[c0] + v1 * hw2[c0 + 1];
                }
                s += __shfl_xor_sync(0xFFFFFFFFu, s, 1);
                s += __shfl_xor_sync(0xFFFFFFFFu, s, 2);
                if ((lane & 3) == 0) {
                    int R = bm + (wm << 6) + (mt << 4) + (lane >> 2) + h * 8;
                    atomicAdd(&d_scores[R], s);
                }
            }
        return;
    }

#pragma unroll
    for (int mt = 0; mt < 4; mt++)
#pragma unroll
        for (int nt = 0; nt < 8; nt++) {
            int r0 = bm + (wm << 6) + (mt << 4) + (lane >> 2);
            int c0 = bn + (wn << 6) + (nt << 3) + ((lane & 3) << 1);
            float2 bb = *(const float2*)&bias[c0];
#pragma unroll
            for (int h = 0; h < 2; h++) {
                int R = r0 + h * 8;
                float v0 = acc[mt][nt][h * 2 + 0] + bb.x;
                float v1 = acc[mt][nt][h * 2 + 1] + bb.y;
                if (MODE == 0) { v0 = fmaxf(v0, 0.0f); v1 = fmaxf(v1, 0.0f); }
                *(__half2*)&C[(size_t)R * Nn + c0] =
                    __halves2half2(__float2half(v0), __float2half(v1));
            }
        }
}

// ---------------- pass-2 fp32 SGEMM (validated, 128x128) ----------------
#define BM 128
#define BN 128
#define BKK 16
template <bool RELU>
__global__ __launch_bounds__(256) void sgemm_bias_kernel(
    const float* __restrict__ A, const float* __restrict__ W,
    const float* __restrict__ bias, float* __restrict__ C,
    int M, int K, int Nn)
{
    __shared__ float As[BKK][BM];
    __shared__ float Bs[BKK][BN];
    const int tid = threadIdx.x;
    const int bm = blockIdx.y * BM;
    const int bn = blockIdx.x * BN;
    const int tx = tid & 15;
    const int ty = tid >> 4;
    float acc[8][8];
#pragma unroll
    for (int i = 0; i < 8; i++)
#pragma unroll
        for (int j = 0; j < 8; j++) acc[i][j] = 0.0f;
    const int q0 = tid * 2;
    for (int k0 = 0; k0 < K; k0 += BKK) {
#pragma unroll
        for (int l = 0; l < 2; l++) {
            int q = q0 + l;
            int row = q >> 2;
            int col = (q & 3) * 4;
            float4 v = *(const float4*)&A[(size_t)(bm + row) * K + k0 + col];
            As[col + 0][row] = v.x; As[col + 1][row] = v.y;
            As[col + 2][row] = v.z; As[col + 3][row] = v.w;
        }
#pragma unroll
        for (int l = 0; l < 2; l++) {
            int q = q0 + l;
            int row = q >> 5;
            int col = (q & 31) * 4;
            *(float4*)&Bs[row][col] = *(const float4*)&W[(size_t)(k0 + row) * Nn + bn + col];
        }
        __syncthreads();
#pragma unroll
        for (int kk = 0; kk < BKK; kk++) {
            float a[8], b[8];
            float4 a0 = *(const float4*)&As[kk][ty * 8];
            float4 a1 = *(const float4*)&As[kk][ty * 8 + 4];
            a[0]=a0.x; a[1]=a0.y; a[2]=a0.z; a[3]=a0.w;
            a[4]=a1.x; a[5]=a1.y; a[6]=a1.z; a[7]=a1.w;
            float4 b0 = *(const float4*)&Bs[kk][tx * 8];
            float4 b1 = *(const float4*)&Bs[kk][tx * 8 + 4];
            b[0]=b0.x; b[1]=b0.y; b[2]=b0.z; b[3]=b0.w;
            b[4]=b1.x; b[5]=b1.y; b[6]=b1.z; b[7]=b1.w;
#pragma unroll
            for (int i = 0; i < 8; i++)
#pragma unroll
                for (int j = 0; j < 8; j++) acc[i][j] += a[i] * b[j];
        }
        __syncthreads();
    }
#pragma unroll
    for (int i = 0; i < 8; i++) {
        int row = bm + ty * 8 + i;
#pragma unroll
        for (int j = 0; j < 8; j += 4) {
            int col = bn + tx * 8 + j;
            float4 v;
            v.x = acc[i][j+0] + bias[col+0]; v.y = acc[i][j+1] + bias[col+1];
            v.z = acc[i][j+2] + bias[col+2]; v.w = acc[i][j+3] + bias[col+3];
            if (RELU) { v.x=fmaxf(v.x,0.f); v.y=fmaxf(v.y,0.f); v.z=fmaxf(v.z,0.f); v.w=fmaxf(v.w,0.f); }
            *(float4*)&C[(size_t)row * Nn + col] = v;
        }
    }
}

// ---------------- exact score for candidates ----------------
__global__ __launch_bounds__(256) void cscore_kernel(
    const float* __restrict__ hw2, const float* __restrict__ hb2)
{
    int gt = blockIdx.x * blockDim.x + threadIdx.x;
    int c = gt >> 5, lane = gt & 31;
    if (c >= CTOT) return;
    const float* row = d_cg + (size_t)c * 384;
    float s = 0.0f;
#pragma unroll
    for (int j = 0; j < 384; j += 32) s += row[j + lane] * hw2[j + lane];
#pragma unroll
    for (int o = 16; o > 0; o >>= 1) s += __shfl_down_sync(0xFFFFFFFFu, s, o);
    if (lane == 0) d_cscore[c] = s + hb2[0];
}

// ---------------- offsets ----------------
__global__ void offsets_kernel(const int* __restrict__ bids)
{
    int b = threadIdx.x;
    if (b > NBATCH) return;
    if (b == NBATCH) { d_off[NBATCH] = NPTS; return; }
    int lo = 0, hi = NPTS;
    while (lo < hi) { int mid = (lo + hi) >> 1; if (bids[mid] < b) lo = mid + 1; else hi = mid; }
    d_off[b] = lo;
}

__device__ __forceinline__ unsigned int ford(float f)
{
    unsigned int u = __float_as_uint(f);
    return (u & 0x80000000u) ? ~u : (u | 0x80000000u);
}

// ---------------- pass 1: approx top-CPB per batch (1024 threads) ------------
__global__ __launch_bounds__(1024) void topk1_kernel()
{
    __shared__ unsigned long long keys[SORT_N];
    int b = blockIdx.x;
    int base = d_off[b];
    int count = d_off[b + 1] - base;
    for (int t = threadIdx.x; t < SORT_N; t += 1024) {
        unsigned int ordv = (t < count) ? ford(d_scores[base + t]) : 0u;
        keys[t] = ((unsigned long long)ordv << 32) | (unsigned long long)(0xFFFFFFFFu - (unsigned)t);
    }
    __syncthreads();
    for (int k = 2; k <= SORT_N; k <<= 1)
        for (int j = k >> 1; j > 0; j >>= 1) {
            for (int t = threadIdx.x; t < SORT_N; t += 1024) {
                int ixj = t ^ j;
                if (ixj > t) {
                    unsigned long long a = keys[t], c = keys[ixj];
                    bool up = ((t & k) == 0);
                    if (up ? (a < c) : (a > c)) { keys[t] = c; keys[ixj] = a; }
                }
            }
            __syncthreads();
        }
    if (threadIdx.x < CPB) {
        unsigned int low = (unsigned int)(keys[threadIdx.x] & 0xFFFFFFFFu);
        d_cand[b * CPB + threadIdx.x] = (int)(0xFFFFFFFFu - low);
    }
}

// ---------------- gather candidate h0 (fp32) ----------------
__global__ __launch_bounds__(96) void gath0c_kernel()
{
    int c = blockIdx.x;
    int b = c / CPB;
    int pos = d_cand[c];
    int count = d_off[b + 1] - d_off[b];
    float v = 0.0f;
    if (pos < count) v = d_h0f[(size_t)(d_off[b] + pos) * 96 + threadIdx.x];
    d_c0[(size_t)c * 96 + threadIdx.x] = v;
}

// ---------------- pass 2: exact top-128 among CPB candidates ----------------
__global__ __launch_bounds__(256) void topk2_kernel()
{
    __shared__ unsigned long long keys[256];
    __shared__ int vals[256];
    int b = blockIdx.x;
    int count = d_off[b + 1] - d_off[b];
    int t = threadIdx.x;
    if (t < CPB) {
        int pos = d_cand[b * CPB + t];
        if (pos < count) {
            keys[t] = ((unsigned long long)ford(d_cscore[b * CPB + t]) << 32) |
                      (unsigned long long)(0xFFFFFFFFu - (unsigned)pos);
        } else {
            keys[t] = (unsigned long long)t;
        }
        vals[t] = t;
    } else {
        keys[t] = (unsigned long long)t;
        vals[t] = -1;
    }
    __syncthreads();
    for (int k = 2; k <= 256; k <<= 1)
        for (int j = k >> 1; j > 0; j >>= 1) {
            int ixj = t ^ j;
            if (ixj > t) {
                unsigned long long a = keys[t], c = keys[ixj];
                bool up = ((t & k) == 0);
                if (up ? (a < c) : (a > c)) {
                    keys[t] = c; keys[ixj] = a;
                    int va = vals[t]; vals[t] = vals[ixj]; vals[ixj] = va;
                }
            }
            __syncthreads();
        }
    if (t < MAX_TOKENS) {
        int jj = vals[t];
        d_fsel_j[b * MAX_TOKENS + t] = jj;
        d_fsel_p[b * MAX_TOKENS + t] = (jj >= 0) ? d_cand[b * CPB + jj] : 0x7FFFFFFF;
    }
}

// ---------------- gather outputs ----------------
__global__ __launch_bounds__(192) void gather_kernel(
    const float* __restrict__ coords, const float* __restrict__ times,
    float* __restrict__ out)
{
    int slot = blockIdx.x;
    int b = slot >> 7;
    int jj = d_fsel_j[slot];
    int pos = d_fsel_p[slot];
    int count = d_off[b + 1] - d_off[b];
    float* tok  = out + (size_t)slot * TOKEN_DIM;
    float* cent = out + TOK_ELEMS + (size_t)slot * 4;
    float* msk  = out + TOK_ELEMS + CENT_ELEMS + slot;
    if (jj >= 0 && pos < count) {
        int i = d_off[b] + pos;
        const float* src = d_cpf + (size_t)(b * CPB + jj) * TOKEN_DIM;
        for (int j = threadIdx.x; j < TOKEN_DIM / 4; j += blockDim.x)
            ((float4*)tok)[j] = ((const float4*)src)[j];
        if (threadIdx.x < 3) cent[threadIdx.x] = coords[(size_t)i * 3 + threadIdx.x];
        if (threadIdx.x == 3) cent[3] = times[i];
        if (threadIdx.x == 0) *msk = 1.0f;
    } else {
        for (int j = threadIdx.x; j < TOKEN_DIM; j += blockDim.x) tok[j] = 0.0f;
        if (threadIdx.x < 4) cent[threadIdx.x] = 0.0f;
        if (threadIdx.x == 0) *msk = 0.0f;
    }
}

// ---------------- launch ----------------
extern "C" void kernel_launch(void* const* d_in, const int* in_sizes, int n_in,
                              void* d_out, int out_size)
{
    const float* coords   = (const float*)d_in[0];
    const float* features = (const float*)d_in[1];
    const float* times    = (const float*)d_in[2];
    const int*   bids     = (const int*)d_in[3];
    const float* ln_g = (const float*)d_in[4];
    const float* ln_b = (const float*)d_in[5];
    const float* sw1 = (const float*)d_in[6];
    const float* sb1 = (const float*)d_in[7];
    const float* sw2 = (const float*)d_in[8];
    const float* sb2 = (const float*)d_in[9];
    const float* mw1 = (const float*)d_in[10];
    const float* mb1 = (const float*)d_in[11];
    const float* mw2 = (const float*)d_in[12];
    const float* mb2 = (const float*)d_in[13];
    const float* mw3 = (const float*)d_in[14];
    const float* mb3 = (const float*)d_in[15];
    const float* mw4 = (const float*)d_in[16];
    const float* mb4 = (const float*)d_in[17];
    const float* hw1 = (const float*)d_in[18];
    const float* hb1 = (const float*)d_in[19];
    const float* hw2 = (const float*)d_in[20];
    const float* hb2 = (const float*)d_in[21];

    cudaFuncSetAttribute(hgemm<0>, cudaFuncAttributeMaxDynamicSharedMemorySize, HG_SMEM);
    cudaFuncSetAttribute(hgemm<1>, cudaFuncAttributeMaxDynamicSharedMemorySize, HG_SMEM);
    cudaFuncSetAttribute(hgemm<2>, cudaFuncAttributeMaxDynamicSharedMemorySize, HG_SMEM);

    __half *acth, *wth;
    float *c0, *c1, *c2, *c3, *cpf, *cg;
    cudaGetSymbolAddress((void**)&acth, d_acth);
    cudaGetSymbolAddress((void**)&wth,  d_wth);
    cudaGetSymbolAddress((void**)&c0,  d_c0);
    cudaGetSymbolAddress((void**)&c1,  d_c1);
    cudaGetSymbolAddress((void**)&c2,  d_c2);
    cudaGetSymbolAddress((void**)&c3,  d_c3);
    cudaGetSymbolAddress((void**)&cpf, d_cpf);
    cudaGetSymbolAddress((void**)&cg,  d_cg);
    float* out = (float*)d_out;

    // Launch order arranged so ncu (-s 5 -c 1) captures hgemm L4 (the biggest).
    wsplit_all<<<(1441792 + 255) / 256, 256>>>(mw1, mw2, mw3, mw4, hw1);                              // 1
    stage_a_kernel<<<NPTS / 128, 128>>>(coords, features, times, ln_g, ln_b, sw1, sb1, sw2, sb2);     // 2
    hgemm<0><<<dim3(2, NPTS / 128), 128, HG_SMEM>>>(acth + HOFF_H0, wth + WOFF_1, mb1, acth + HOFF_H1, nullptr, 128, 256); // 3
    hgemm<0><<<dim3(4, NPTS / 128), 128, HG_SMEM>>>(acth + HOFF_H1, wth + WOFF_2, mb2, acth + HOFF_H2, nullptr, 256, 512); // 4
    hgemm<0><<<dim3(6, NPTS / 128), 128, HG_SMEM>>>(acth + HOFF_H2, wth + WOFF_3, mb3, acth + HOFF_H3, nullptr, 512, 768); // 5
    hgemm<1><<<dim3(6, NPTS / 128), 128, HG_SMEM>>>(acth + HOFF_H3, wth + WOFF_4, mb4, acth + HOFF_PF, nullptr, 768, 768); // 6 <- ncu (L4)
    hgemm<2><<<dim3(3, NPTS / 128), 128, HG_SMEM>>>(acth + HOFF_PF, wth + WOFF_5, hb1, nullptr, hw2, 768, 384);            // 7
    offsets_kernel<<<1, 128>>>(bids);                                                                 // 8

    topk1_kernel<<<NBATCH, 1024>>>();
    gath0c_kernel<<<CTOT, 96>>>();

    // pass 2: exact fp32 chain on candidates (validated 128x128 tiles)
    sgemm_bias_kernel<true ><<<dim3(256 / BN, CTOT / BM), 256>>>(c0,  mw1, mb1, c1,  CTOT,  96, 256);
    sgemm_bias_kernel<true ><<<dim3(512 / BN, CTOT / BM), 256>>>(c1,  mw2, mb2, c2,  CTOT, 256, 512);
    sgemm_bias_kernel<true ><<<dim3(768 / BN, CTOT / BM), 256>>>(c2,  mw3, mb3, c3,  CTOT, 512, 768);
    sgemm_bias_kernel<false><<<dim3(768 / BN, CTOT / BM), 256>>>(c3,  mw4, mb4, cpf, CTOT, 768, 768);
    sgemm_bias_kernel<true ><<<dim3(384 / BN, CTOT / BM), 256>>>(cpf, hw1, hb1, cg,  CTOT, 768, 384);
    cscore_kernel<<<(CTOT * 32 + 255) / 256, 256>>>(hw2, hb2);

    topk2_kernel<<<NBATCH, 256>>>();
    gather_kernel<<<NBATCH * MAX_TOKENS, 192>>>(coords, times, out);
}

// round 14
// speedup vs baseline: 1.1057x; 1.1057x over previous
#include <cuda_runtime.h>
#include <cuda_fp16.h>
#include <math.h>
#include <stdint.h>

#define NPTS        131072
#define NBATCH      64
#define FEAT_DIM    32
#define TOKEN_DIM   768
#define MAX_TOKENS  128
#define SORT_N      4096
#define CPB         144
#define CTOT        (NBATCH * CPB)            // 9216
#define TOK_ELEMS   (NBATCH * MAX_TOKENS * TOKEN_DIM)
#define CENT_ELEMS  (NBATCH * MAX_TOKENS * 4)

// ---------------- Scratch arenas ----------------
#define HOFF_H0 0ULL
#define HOFF_H1 16777216ULL
#define HOFF_H2 50331648ULL
#define HOFF_H3 117440512ULL
#define ACTH_TOT 218103808ULL
__device__ __half d_acth[ACTH_TOT];

#define WOFF_1 0ULL
#define WOFF_2 32768ULL
#define WOFF_3 163840ULL
#define WOFF_4 557056ULL
#define WOFF_5 1146880ULL          // holds fused W45 (384 x 768)
#define WTH_TOT 1441792ULL
__device__ __half d_wth[WTH_TOT];

__device__ float d_h0f[(size_t)NPTS * 96];

// fused score-head weights
__device__ float d_w45f[768 * 384];
__device__ float d_b45[384];
__device__ float d_zero384[384];   // zero-initialized device global, never written

// pass-2 fp32 candidate chain (validated path, 128x128 tiles)
__device__ float d_c0 [(size_t)CTOT * 96];
__device__ float d_c1 [(size_t)CTOT * 256];
__device__ float d_c2 [(size_t)CTOT * 512];
__device__ float d_c3 [(size_t)CTOT * 768];
__device__ float d_cpf[(size_t)CTOT * 768];
__device__ float d_cg [(size_t)CTOT * 384];

__device__ float d_scores[NPTS];
__device__ float d_cscore[CTOT];
__device__ int   d_off[NBATCH + 1];
__device__ int   d_cand[CTOT];
__device__ int   d_fsel_j[NBATCH * MAX_TOKENS];
__device__ int   d_fsel_p[NBATCH * MAX_TOKENS];

// ---------------- PTX helpers ----------------
__device__ __forceinline__ uint32_t smem_u32(const void* p) {
    uint32_t a;
    asm("{ .reg .u64 t; cvta.to.shared.u64 t, %1; cvt.u32.u64 %0, t; }" : "=r"(a) : "l"(p));
    return a;
}
#define CP_ASYNC16(dst, src) \
    asm volatile("cp.async.cg.shared.global [%0], [%1], 16;" :: "r"(dst), "l"(src))
#define CP_COMMIT() asm volatile("cp.async.commit_group;")
#define CP_WAIT(n)  asm volatile("cp.async.wait_group %0;" :: "n"(n))
#define LDMATRIX_X4(r0, r1, r2, r3, addr) \
    asm volatile("ldmatrix.sync.aligned.m8n8.x4.shared.b16 {%0,%1,%2,%3}, [%4];" \
        : "=r"(r0), "=r"(r1), "=r"(r2), "=r"(r3) : "r"(addr))
#define MMA16816(d, a, b) \
    asm volatile("mma.sync.aligned.m16n8k16.row.col.f32.f16.f16.f32 " \
        "{%0,%1,%2,%3}, {%4,%5,%6,%7}, {%8,%9}, {%0,%1,%2,%3};" \
        : "+f"((d)[0]), "+f"((d)[1]), "+f"((d)[2]), "+f"((d)[3]) \
        : "r"((a)[0]), "r"((a)[1]), "r"((a)[2]), "r"((a)[3]), \
          "r"((b)[0]), "r"((b)[1]))

// ---------------- fused weight convert (4 matrices) ----------------
// Each: W[K,Nn] fp32 -> [Nn,Kpad] fp16 (transposed, K padded)
__global__ void wsplit_all(const float* __restrict__ W1, const float* __restrict__ W2,
                           const float* __restrict__ W3, const float* __restrict__ W4)
{
    int idx = blockIdx.x * blockDim.x + threadIdx.x;
    const float* W; __half* t; int K, Kpad, Nn;
    if (idx < 32768)        { W = W1; t = d_wth + WOFF_1; K =  96; Kpad = 128; Nn = 256; }
    else if (idx < 163840)  { W = W2; t = d_wth + WOFF_2; K = 256; Kpad = 256; Nn = 512; idx -= 32768; }
    else if (idx < 557056)  { W = W3; t = d_wth + WOFF_3; K = 512; Kpad = 512; Nn = 768; idx -= 163840; }
    else if (idx < 1146880) { W = W4; t = d_wth + WOFF_4; K = 768; Kpad = 768; Nn = 768; idx -= 557056; }
    else return;
    int n = idx / Kpad, k = idx - n * Kpad;
    t[idx] = __float2half((k < K) ? W[(size_t)k * Nn + n] : 0.0f);
}

// standalone convert (for fused W45)
__global__ void wsplit_h(const float* __restrict__ W, __half* __restrict__ t,
                         int K, int Kpad, int Nn)
{
    int idx = blockIdx.x * blockDim.x + threadIdx.x;
    if (idx >= Nn * Kpad) return;
    int n = idx / Kpad, k = idx - n * Kpad;
    t[idx] = __float2half((k < K) ? W[(size_t)k * Nn + n] : 0.0f);
}

// b45[j] = hb1[j] + sum_k mb4[k] * hw1[k,j]
__global__ void b45_kernel(const float* __restrict__ mb4, const float* __restrict__ hw1,
                           const float* __restrict__ hb1)
{
    int j = blockIdx.x * blockDim.x + threadIdx.x;
    if (j >= 384) return;
    float s = hb1[j];
    for (int k = 0; k < 768; k++) s += mb4[k] * hw1[(size_t)k * 384 + j];
    d_b45[j] = s;
}

// ---------------- Stage A (+ zero scores fused) ----------------
__global__ __launch_bounds__(128) void stage_a_kernel(
    const float* __restrict__ coords, const float* __restrict__ features,
    const float* __restrict__ times,
    const float* __restrict__ ln_g, const float* __restrict__ ln_b,
    const float* __restrict__ sw1, const float* __restrict__ sb1,
    const float* __restrict__ sw2, const float* __restrict__ sb2)
{
    __shared__ float s1[256], s2[4096], sb1s[64], sb2s[64], lg[4], lb[4];
    for (int t = threadIdx.x; t < 256; t += 128)  s1[t] = sw1[t];
    for (int t = threadIdx.x; t < 4096; t += 128) s2[t] = sw2[t];
    if (threadIdx.x < 64) { sb1s[threadIdx.x] = sb1[threadIdx.x]; sb2s[threadIdx.x] = sb2[threadIdx.x]; }
    if (threadIdx.x < 4)  { lg[threadIdx.x] = ln_g[threadIdx.x]; lb[threadIdx.x] = ln_b[threadIdx.x]; }
    __syncthreads();

    int i = blockIdx.x * 128 + threadIdx.x;
    d_scores[i] = 0.0f;                      // fused zero-init (before hgemm<2> atomics)

    float x0 = coords[i * 3 + 0], x1 = coords[i * 3 + 1], x2 = coords[i * 3 + 2], x3 = times[i];
    float mu = 0.25f * (x0 + x1 + x2 + x3);
    float e0 = x0 - mu, e1 = x1 - mu, e2 = x2 - mu, e3 = x3 - mu;
    float inv = 1.0f / sqrtf(0.25f * (e0*e0 + e1*e1 + e2*e2 + e3*e3) + 1e-5f);
    float xn0 = e0*inv*lg[0]+lb[0], xn1 = e1*inv*lg[1]+lb[1];
    float xn2 = e2*inv*lg[2]+lb[2], xn3 = e3*inv*lg[3]+lb[3];

    float t1[64];
#pragma unroll
    for (int j = 0; j < 64; j++) {
        float a = sb1s[j] + xn0*s1[j] + xn1*s1[64+j] + xn2*s1[128+j] + xn3*s1[192+j];
        t1[j] = fmaxf(a, 0.0f);
    }

    float*  hf = d_h0f + (size_t)i * 96;
    __half* hh = d_acth + HOFF_H0 + (size_t)i * 128;

#pragma unroll
    for (int c = 0; c < FEAT_DIM; c++) {
        float v = features[(size_t)i * FEAT_DIM + c];
        hf[c] = v; hh[c] = __float2half(v);
    }
    for (int j = 0; j < 64; j++) {
        float a = sb2s[j];
#pragma unroll
        for (int kk = 0; kk < 64; kk++) a += t1[kk] * s2[kk * 64 + j];
        a = fmaxf(a, 0.0f);
        hf[32 + j] = a; hh[32 + j] = __float2half(a);
    }
    __half z = __float2half(0.0f);
#pragma unroll
    for (int c = 96; c < 128; c++) hh[c] = z;
}

// ---------------- pass-1 fp16 HGEMM (4 warps, 64x64 warp tiles) --------------
#define STAGES      4
#define STAGE_BYTES 16384
#define HG_SMEM     (STAGES * STAGE_BYTES)

// MODE: 0 = relu -> fp16 C; 2 = relu+score (no C write)
template <int MODE>
__global__ __launch_bounds__(128) void hgemm(
    const __half* __restrict__ A, const __half* __restrict__ B,
    const float* __restrict__ bias, __half* __restrict__ C,
    const float* __restrict__ hw2,
    int K, int Nn)
{
    extern __shared__ char smraw[];
    const uint32_t sb = smem_u32(smraw);
    const int tid = threadIdx.x;
    const int lane = tid & 31, wid = tid >> 5;
    const int wm = wid & 1, wn = wid >> 1;
    const int bm = blockIdx.y << 7, bn = blockIdx.x << 7;
    const int nIters = K >> 5;

    float acc[4][8][4];
#pragma unroll
    for (int a = 0; a < 4; a++)
#pragma unroll
        for (int b = 0; b < 8; b++)
#pragma unroll
            for (int c = 0; c < 4; c++) acc[a][b][c] = 0.0f;

    auto load_stage = [&](int s) {
        uint32_t base = sb + (uint32_t)(s % STAGES) * STAGE_BYTES;
        int k0 = s << 5;
#pragma unroll
        for (int t = 0; t < 8; t++) {
            int q = tid + (t << 7);
            int sec = q >> 9;
            int idx = q & 511;
            int row = idx >> 2;
            int c = idx & 3;
            uint32_t dst = base + (sec << 13) + row * 64 + ((c ^ ((row >> 1) & 3)) << 4);
            const __half* gp = (sec == 0)
                ? A + (size_t)(bm + row) * K + k0 + (c << 3)
                : B + (size_t)(bn + row) * K + k0 + (c << 3);
            CP_ASYNC16(dst, gp);
        }
    };

#pragma unroll
    for (int s = 0; s < STAGES - 1; s++) {
        if (s < nIters) load_stage(s);
        CP_COMMIT();
    }

    for (int it = 0; it < nIters; it++) {
        CP_WAIT(STAGES - 2);
        __syncthreads();
        int nx = it + STAGES - 1;
        if (nx < nIters) load_stage(nx);
        CP_COMMIT();

        uint32_t base = sb + (uint32_t)(it % STAGES) * STAGE_BYTES;
#pragma unroll
        for (int k16 = 0; k16 < 2; k16++) {
            uint32_t af[4][4];
#pragma unroll
            for (int mt = 0; mt < 4; mt++) {
                int row = (wm << 6) + (mt << 4) + (lane & 15);
                int ch = (k16 << 1) + (lane >> 4);
                uint32_t ad = base + row * 64 + ((ch ^ ((row >> 1) & 3)) << 4);
                LDMATRIX_X4(af[mt][0], af[mt][1], af[mt][2], af[mt][3], ad);
            }
            uint32_t bfr[8][2];
#pragma unroll
            for (int pair = 0; pair < 4; pair++) {
                int row = (wn << 6) + (pair << 4) + (((lane >> 4) & 1) << 3) + (lane & 7);
                int ch = (k16 << 1) + ((lane >> 3) & 1);
                uint32_t ad = base + 8192 + row * 64 + ((ch ^ ((row >> 1) & 3)) << 4);
                uint32_t r0, r1, r2, r3;
                LDMATRIX_X4(r0, r1, r2, r3, ad);
                bfr[pair * 2][0] = r0;      bfr[pair * 2][1] = r1;
                bfr[pair * 2 + 1][0] = r2;  bfr[pair * 2 + 1][1] = r3;
            }
#pragma unroll
            for (int mt = 0; mt < 4; mt++)
#pragma unroll
                for (int nt = 0; nt < 8; nt++)
                    MMA16816(acc[mt][nt], af[mt], bfr[nt]);
        }
    }

    if (MODE == 2) {
#pragma unroll
        for (int mt = 0; mt < 4; mt++)
#pragma unroll
            for (int h = 0; h < 2; h++) {
                float s = 0.0f;
#pragma unroll
                for (int nt = 0; nt < 8; nt++) {
                    int c0 = bn + (wn << 6) + (nt << 3) + ((lane & 3) << 1);
                    float v0 = fmaxf(acc[mt][nt][h * 2 + 0] + bias[c0], 0.0f);
                    float v1 = fmaxf(acc[mt][nt][h * 2 + 1] + bias[c0 + 1], 0.0f);
                    s += v0 * hw2[c0] + v1 * hw2[c0 + 1];
                }
                s += __shfl_xor_sync(0xFFFFFFFFu, s, 1);
                s += __shfl_xor_sync(0xFFFFFFFFu, s, 2);
                if ((lane & 3) == 0) {
                    int R = bm + (wm << 6) + (mt << 4) + (lane >> 2) + h * 8;
                    atomicAdd(&d_scores[R], s);
                }
            }
        return;
    }

#pragma unroll
    for (int mt = 0; mt < 4; mt++)
#pragma unroll
        for (int nt = 0; nt < 8; nt++) {
            int r0 = bm + (wm << 6) + (mt << 4) + (lane >> 2);
            int c0 = bn + (wn << 6) + (nt << 3) + ((lane & 3) << 1);
            float2 bb = *(const float2*)&bias[c0];
#pragma unroll
            for (int h = 0; h < 2; h++) {
                int R = r0 + h * 8;
                float v0 = fmaxf(acc[mt][nt][h * 2 + 0] + bb.x, 0.0f);
                float v1 = fmaxf(acc[mt][nt][h * 2 + 1] + bb.y, 0.0f);
                *(__half2*)&C[(size_t)R * Nn + c0] =
                    __halves2half2(__float2half(v0), __float2half(v1));
            }
        }
}

// ---------------- fp32 SGEMM (validated, 128x128) ----------------
#define BM 128
#define BN 128
#define BKK 16
template <bool RELU>
__global__ __launch_bounds__(256) void sgemm_bias_kernel(
    const float* __restrict__ A, const float* __restrict__ W,
    const float* __restrict__ bias, float* __restrict__ C,
    int M, int K, int Nn)
{
    __shared__ float As[BKK][BM];
    __shared__ float Bs[BKK][BN];
    const int tid = threadIdx.x;
    const int bm = blockIdx.y * BM;
    const int bn = blockIdx.x * BN;
    const int tx = tid & 15;
    const int ty = tid >> 4;
    float acc[8][8];
#pragma unroll
    for (int i = 0; i < 8; i++)
#pragma unroll
        for (int j = 0; j < 8; j++) acc[i][j] = 0.0f;
    const int q0 = tid * 2;
    for (int k0 = 0; k0 < K; k0 += BKK) {
#pragma unroll
        for (int l = 0; l < 2; l++) {
            int q = q0 + l;
            int row = q >> 2;
            int col = (q & 3) * 4;
            float4 v = *(const float4*)&A[(size_t)(bm + row) * K + k0 + col];
            As[col + 0][row] = v.x; As[col + 1][row] = v.y;
            As[col + 2][row] = v.z; As[col + 3][row] = v.w;
        }
#pragma unroll
        for (int l = 0; l < 2; l++) {
            int q = q0 + l;
            int row = q >> 5;
            int col = (q & 31) * 4;
            *(float4*)&Bs[row][col] = *(const float4*)&W[(size_t)(k0 + row) * Nn + bn + col];
        }
        __syncthreads();
#pragma unroll
        for (int kk = 0; kk < BKK; kk++) {
            float a[8], b[8];
            float4 a0 = *(const float4*)&As[kk][ty * 8];
            float4 a1 = *(const float4*)&As[kk][ty * 8 + 4];
            a[0]=a0.x; a[1]=a0.y; a[2]=a0.z; a[3]=a0.w;
            a[4]=a1.x; a[5]=a1.y; a[6]=a1.z; a[7]=a1.w;
            float4 b0 = *(const float4*)&Bs[kk][tx * 8];
            float4 b1 = *(const float4*)&Bs[kk][tx * 8 + 4];
            b[0]=b0.x; b[1]=b0.y; b[2]=b0.z; b[3]=b0.w;
            b[4]=b1.x; b[5]=b1.y; b[6]=b1.z; b[7]=b1.w;
#pragma unroll
            for (int i = 0; i < 8; i++)
#pragma unroll
                for (int j = 0; j < 8; j++) acc[i][j] += a[i] * b[j];
        }
        __syncthreads();
    }
#pragma unroll
    for (int i = 0; i < 8; i++) {
        int row = bm + ty * 8 + i;
#pragma unroll
        for (int j = 0; j < 8; j += 4) {
            int col = bn + tx * 8 + j;
            float4 v;
            v.x = acc[i][j+0] + bias[col+0]; v.y = acc[i][j+1] + bias[col+1];
            v.z = acc[i][j+2] + bias[col+2]; v.w = acc[i][j+3] + bias[col+3];
            if (RELU) { v.x=fmaxf(v.x,0.f); v.y=fmaxf(v.y,0.f); v.z=fmaxf(v.z,0.f); v.w=fmaxf(v.w,0.f); }
            *(float4*)&C[(size_t)row * Nn + col] = v;
        }
    }
}

// ---------------- exact score for candidates ----------------
__global__ __launch_bounds__(256) void cscore_kernel(
    const float* __restrict__ hw2, const float* __restrict__ hb2)
{
    int gt = blockIdx.x * blockDim.x + threadIdx.x;
    int c = gt >> 5, lane = gt & 31;
    if (c >= CTOT) return;
    const float* row = d_cg + (size_t)c * 384;
    float s = 0.0f;
#pragma unroll
    for (int j = 0; j < 384; j += 32) s += row[j + lane] * hw2[j + lane];
#pragma unroll
    for (int o = 16; o > 0; o >>= 1) s += __shfl_down_sync(0xFFFFFFFFu, s, o);
    if (lane == 0) d_cscore[c] = s + hb2[0];
}

// ---------------- offsets ----------------
__global__ void offsets_kernel(const int* __restrict__ bids)
{
    int b = threadIdx.x;
    if (b > NBATCH) return;
    if (b == NBATCH) { d_off[NBATCH] = NPTS; return; }
    int lo = 0, hi = NPTS;
    while (lo < hi) { int mid = (lo + hi) >> 1; if (bids[mid] < b) lo = mid + 1; else hi = mid; }
    d_off[b] = lo;
}

__device__ __forceinline__ unsigned int ford(float f)
{
    unsigned int u = __float_as_uint(f);
    return (u & 0x80000000u) ? ~u : (u | 0x80000000u);
}

// ---------------- pass 1: approx top-CPB per batch (1024 threads) ------------
__global__ __launch_bounds__(1024) void topk1_kernel()
{
    __shared__ unsigned long long keys[SORT_N];
    int b = blockIdx.x;
    int base = d_off[b];
    int count = d_off[b + 1] - base;
    for (int t = threadIdx.x; t < SORT_N; t += 1024) {
        unsigned int ordv = (t < count) ? ford(d_scores[base + t]) : 0u;
        keys[t] = ((unsigned long long)ordv << 32) | (unsigned long long)(0xFFFFFFFFu - (unsigned)t);
    }
    __syncthreads();
    for (int k = 2; k <= SORT_N; k <<= 1)
        for (int j = k >> 1; j > 0; j >>= 1) {
            for (int t = threadIdx.x; t < SORT_N; t += 1024) {
                int ixj = t ^ j;
                if (ixj > t) {
                    unsigned long long a = keys[t], c = keys[ixj];
                    bool up = ((t & k) == 0);
                    if (up ? (a < c) : (a > c)) { keys[t] = c; keys[ixj] = a; }
                }
            }
            __syncthreads();
        }
    if (threadIdx.x < CPB) {
        unsigned int low = (unsigned int)(keys[threadIdx.x] & 0xFFFFFFFFu);
        d_cand[b * CPB + threadIdx.x] = (int)(0xFFFFFFFFu - low);
    }
}

// ---------------- gather candidate h0 (fp32) ----------------
__global__ __launch_bounds__(96) void gath0c_kernel()
{
    int c = blockIdx.x;
    int b = c / CPB;
    int pos = d_cand[c];
    int count = d_off[b + 1] - d_off[b];
    float v = 0.0f;
    if (pos < count) v = d_h0f[(size_t)(d_off[b] + pos) * 96 + threadIdx.x];
    d_c0[(size_t)c * 96 + threadIdx.x] = v;
}

// ---------------- pass 2: exact top-128 among CPB candidates ----------------
__global__ __launch_bounds__(256) void topk2_kernel()
{
    __shared__ unsigned long long keys[256];
    __shared__ int vals[256];
    int b = blockIdx.x;
    int count = d_off[b + 1] - d_off[b];
    int t = threadIdx.x;
    if (t < CPB) {
        int pos = d_cand[b * CPB + t];
        if (pos < count) {
            keys[t] = ((unsigned long long)ford(d_cscore[b * CPB + t]) << 32) |
                      (unsigned long long)(0xFFFFFFFFu - (unsigned)pos);
        } else {
            keys[t] = (unsigned long long)t;
        }
        vals[t] = t;
    } else {
        keys[t] = (unsigned long long)t;
        vals[t] = -1;
    }
    __syncthreads();
    for (int k = 2; k <= 256; k <<= 1)
        for (int j = k >> 1; j > 0; j >>= 1) {
            int ixj = t ^ j;
            if (ixj > t) {
                unsigned long long a = keys[t], c = keys[ixj];
                bool up = ((t & k) == 0);
                if (up ? (a < c) : (a > c)) {
                    keys[t] = c; keys[ixj] = a;
                    int va = vals[t]; vals[t] = vals[ixj]; vals[ixj] = va;
                }
            }
            __syncthreads();
        }
    if (t < MAX_TOKENS) {
        int jj = vals[t];
        d_fsel_j[b * MAX_TOKENS + t] = jj;
        d_fsel_p[b * MAX_TOKENS + t] = (jj >= 0) ? d_cand[b * CPB + jj] : 0x7FFFFFFF;
    }
}

// ---------------- gather outputs ----------------
__global__ __launch_bounds__(192) void gather_kernel(
    const float* __restrict__ coords, const float* __restrict__ times,
    float* __restrict__ out)
{
    int slot = blockIdx.x;
    int b = slot >> 7;
    int jj = d_fsel_j[slot];
    int pos = d_fsel_p[slot];
    int count = d_off[b + 1] - d_off[b];
    float* tok  = out + (size_t)slot * TOKEN_DIM;
    float* cent = out + TOK_ELEMS + (size_t)slot * 4;
    float* msk  = out + TOK_ELEMS + CENT_ELEMS + slot;
    if (jj >= 0 && pos < count) {
        int i = d_off[b] + pos;
        const float* src = d_cpf + (size_t)(b * CPB + jj) * TOKEN_DIM;
        for (int j = threadIdx.x; j < TOKEN_DIM / 4; j += blockDim.x)
            ((float4*)tok)[j] = ((const float4*)src)[j];
        if (threadIdx.x < 3) cent[threadIdx.x] = coords[(size_t)i * 3 + threadIdx.x];
        if (threadIdx.x == 3) cent[3] = times[i];
        if (threadIdx.x == 0) *msk = 1.0f;
    } else {
        for (int j = threadIdx.x; j < TOKEN_DIM; j += blockDim.x) tok[j] = 0.0f;
        if (threadIdx.x < 4) cent[threadIdx.x] = 0.0f;
        if (threadIdx.x == 0) *msk = 0.0f;
    }
}

// ---------------- launch ----------------
extern "C" void kernel_launch(void* const* d_in, const int* in_sizes, int n_in,
                              void* d_out, int out_size)
{
    const float* coords   = (const float*)d_in[0];
    const float* features = (const float*)d_in[1];
    const float* times    = (const float*)d_in[2];
    const int*   bids     = (const int*)d_in[3];
    const float* ln_g = (const float*)d_in[4];
    const float* ln_b = (const float*)d_in[5];
    const float* sw1 = (const float*)d_in[6];
    const float* sb1 = (const float*)d_in[7];
    const float* sw2 = (const float*)d_in[8];
    const float* sb2 = (const float*)d_in[9];
    const float* mw1 = (const float*)d_in[10];
    const float* mb1 = (const float*)d_in[11];
    const float* mw2 = (const float*)d_in[12];
    const float* mb2 = (const float*)d_in[13];
    const float* mw3 = (const float*)d_in[14];
    const float* mb3 = (const float*)d_in[15];
    const float* mw4 = (const float*)d_in[16];
    const float* mb4 = (const float*)d_in[17];
    const float* hw1 = (const float*)d_in[18];
    const float* hb1 = (const float*)d_in[19];
    const float* hw2 = (const float*)d_in[20];
    const float* hb2 = (const float*)d_in[21];

    cudaFuncSetAttribute(hgemm<0>, cudaFuncAttributeMaxDynamicSharedMemorySize, HG_SMEM);
    cudaFuncSetAttribute(hgemm<2>, cudaFuncAttributeMaxDynamicSharedMemorySize, HG_SMEM);

    __half *acth, *wth;
    float *c0, *c1, *c2, *c3, *cpf, *cg, *w45f, *b45p, *zeros;
    cudaGetSymbolAddress((void**)&acth, d_acth);
    cudaGetSymbolAddress((void**)&wth,  d_wth);
    cudaGetSymbolAddress((void**)&c0,  d_c0);
    cudaGetSymbolAddress((void**)&c1,  d_c1);
    cudaGetSymbolAddress((void**)&c2,  d_c2);
    cudaGetSymbolAddress((void**)&c3,  d_c3);
    cudaGetSymbolAddress((void**)&cpf, d_cpf);
    cudaGetSymbolAddress((void**)&cg,  d_cg);
    cudaGetSymbolAddress((void**)&w45f, d_w45f);
    cudaGetSymbolAddress((void**)&b45p, d_b45);
    cudaGetSymbolAddress((void**)&zeros, d_zero384);
    float* out = (float*)d_out;

    // Launch order arranged so ncu (-s 5 -c 1) captures hgemm L3 (biggest remaining).
    wsplit_all<<<(1146880 + 255) / 256, 256>>>(mw1, mw2, mw3, mw4);                                   // 1
    stage_a_kernel<<<NPTS / 128, 128>>>(coords, features, times, ln_g, ln_b, sw1, sb1, sw2, sb2);     // 2
    hgemm<0><<<dim3(2, NPTS / 128), 128, HG_SMEM>>>(acth + HOFF_H0, wth + WOFF_1, mb1, acth + HOFF_H1, nullptr, 128, 256); // 3
    hgemm<0><<<dim3(4, NPTS / 128), 128, HG_SMEM>>>(acth + HOFF_H1, wth + WOFF_2, mb2, acth + HOFF_H2, nullptr, 256, 512); // 4
    // W45 = mw4 @ hw1  (fp32, 768x384)
    sgemm_bias_kernel<false><<<dim3(384 / BN, 768 / BM), 256>>>(mw4, hw1, zeros, w45f, 768, 768, 384); // 5
    hgemm<0><<<dim3(6, NPTS / 128), 128, HG_SMEM>>>(acth + HOFF_H2, wth + WOFF_3, mb3, acth + HOFF_H3, nullptr, 512, 768); // 6 <- ncu (L3)
    b45_kernel<<<2, 192>>>(mb4, hw1, hb1);                                                            // 7
    wsplit_h<<<(384 * 768 + 255) / 256, 256>>>(w45f, wth + WOFF_5, 768, 768, 384);                    // 8
    // fused L4+L5 score head: scores = relu(h3 @ W45 + b45) . hw2
    hgemm<2><<<dim3(3, NPTS / 128), 128, HG_SMEM>>>(acth + HOFF_H3, wth + WOFF_5, b45p, nullptr, hw2, 768, 384); // 9
    offsets_kernel<<<1, 128>>>(bids);                                                                 // 10

    topk1_kernel<<<NBATCH, 1024>>>();
    gath0c_kernel<<<CTOT, 96>>>();

    // pass 2: exact fp32 chain on candidates (validated 128x128 tiles; full L4+L5)
    sgemm_bias_kernel<true ><<<dim3(256 / BN, CTOT / BM), 256>>>(c0,  mw1, mb1, c1,  CTOT,  96, 256);
    sgemm_bias_kernel<true ><<<dim3(512 / BN, CTOT / BM), 256>>>(c1,  mw2, mb2, c2,  CTOT, 256, 512);
    sgemm_bias_kernel<true ><<<dim3(768 / BN, CTOT / BM), 256>>>(c2,  mw3, mb3, c3,  CTOT, 512, 768);
    sgemm_bias_kernel<false><<<dim3(768 / BN, CTOT / BM), 256>>>(c3,  mw4, mb4, cpf, CTOT, 768, 768);
    sgemm_bias_kernel<true ><<<dim3(384 / BN, CTOT / BM), 256>>>(cpf, hw1, hb1, cg,  CTOT, 768, 384);
    cscore_kernel<<<(CTOT * 32 + 255) / 256, 256>>>(hw2, hb2);

    topk2_kernel<<<NBATCH, 256>>>();
    gather_kernel<<<NBATCH * MAX_TOKENS, 192>>>(coords, times, out);
}

// round 15
// speedup vs baseline: 1.1216x; 1.0144x over previous
#include <cuda_runtime.h>
#include <cuda_fp16.h>
#include <math.h>
#include <stdint.h>

#define NPTS        131072
#define NBATCH      64
#define FEAT_DIM    32
#define TOKEN_DIM   768
#define MAX_TOKENS  128
#define SORT_N      4096
#define CPB         144
#define CTOT        (NBATCH * CPB)            // 9216
#define TOK_ELEMS   (NBATCH * MAX_TOKENS * TOKEN_DIM)
#define CENT_ELEMS  (NBATCH * MAX_TOKENS * 4)

// ---------------- Scratch arenas ----------------
#define HOFF_H0 0ULL
#define HOFF_H1 16777216ULL
#define HOFF_H2 50331648ULL
#define HOFF_H3 117440512ULL
#define ACTH_TOT 218103808ULL
__device__ __half d_acth[ACTH_TOT];

#define WOFF_1 0ULL
#define WOFF_2 32768ULL
#define WOFF_3 163840ULL
#define WOFF_4 557056ULL
#define WOFF_5 1146880ULL          // holds fused W45 (384 x 768)
#define WTH_TOT 1441792ULL
__device__ __half d_wth[WTH_TOT];

__device__ float d_h0f[(size_t)NPTS * 96];

// fused score-head weights
__device__ float d_w45f[768 * 384];
__device__ float d_b45[384];
__device__ float d_zero384[384];   // zero-initialized device global, never written

// pass-2 fp32 candidate chain (validated path, 128x128 tiles)
__device__ float d_c0 [(size_t)CTOT * 96];
__device__ float d_c1 [(size_t)CTOT * 256];
__device__ float d_c2 [(size_t)CTOT * 512];
__device__ float d_c3 [(size_t)CTOT * 768];
__device__ float d_cpf[(size_t)CTOT * 768];
__device__ float d_cg [(size_t)CTOT * 384];

__device__ float d_scores[NPTS];
__device__ float d_cscore[CTOT];
__device__ int   d_off[NBATCH + 1];
__device__ int   d_cand[CTOT];
__device__ int   d_fsel_j[NBATCH * MAX_TOKENS];
__device__ int   d_fsel_p[NBATCH * MAX_TOKENS];

// ---------------- PTX helpers ----------------
__device__ __forceinline__ uint32_t smem_u32(const void* p) {
    uint32_t a;
    asm("{ .reg .u64 t; cvta.to.shared.u64 t, %1; cvt.u32.u64 %0, t; }" : "=r"(a) : "l"(p));
    return a;
}
#define CP_ASYNC16(dst, src) \
    asm volatile("cp.async.cg.shared.global [%0], [%1], 16;" :: "r"(dst), "l"(src))
#define CP_COMMIT() asm volatile("cp.async.commit_group;")
#define CP_WAIT(n)  asm volatile("cp.async.wait_group %0;" :: "n"(n))
#define LDMATRIX_X4(r0, r1, r2, r3, addr) \
    asm volatile("ldmatrix.sync.aligned.m8n8.x4.shared.b16 {%0,%1,%2,%3}, [%4];" \
        : "=r"(r0), "=r"(r1), "=r"(r2), "=r"(r3) : "r"(addr))
#define MMA16816(d, a, b) \
    asm volatile("mma.sync.aligned.m16n8k16.row.col.f32.f16.f16.f32 " \
        "{%0,%1,%2,%3}, {%4,%5,%6,%7}, {%8,%9}, {%0,%1,%2,%3};" \
        : "+f"((d)[0]), "+f"((d)[1]), "+f"((d)[2]), "+f"((d)[3]) \
        : "r"((a)[0]), "r"((a)[1]), "r"((a)[2]), "r"((a)[3]), \
          "r"((b)[0]), "r"((b)[1]))

// ---------------- fused weight convert (4 matrices) ----------------
__global__ void wsplit_all(const float* __restrict__ W1, const float* __restrict__ W2,
                           const float* __restrict__ W3, const float* __restrict__ W4)
{
    int idx = blockIdx.x * blockDim.x + threadIdx.x;
    const float* W; __half* t; int K, Kpad, Nn;
    if (idx < 32768)        { W = W1; t = d_wth + WOFF_1; K =  96; Kpad = 128; Nn = 256; }
    else if (idx < 163840)  { W = W2; t = d_wth + WOFF_2; K = 256; Kpad = 256; Nn = 512; idx -= 32768; }
    else if (idx < 557056)  { W = W3; t = d_wth + WOFF_3; K = 512; Kpad = 512; Nn = 768; idx -= 163840; }
    else if (idx < 1146880) { W = W4; t = d_wth + WOFF_4; K = 768; Kpad = 768; Nn = 768; idx -= 557056; }
    else return;
    int n = idx / Kpad, k = idx - n * Kpad;
    t[idx] = __float2half((k < K) ? W[(size_t)k * Nn + n] : 0.0f);
}

__global__ void wsplit_h(const float* __restrict__ W, __half* __restrict__ t,
                         int K, int Kpad, int Nn)
{
    int idx = blockIdx.x * blockDim.x + threadIdx.x;
    if (idx >= Nn * Kpad) return;
    int n = idx / Kpad, k = idx - n * Kpad;
    t[idx] = __float2half((k < K) ? W[(size_t)k * Nn + n] : 0.0f);
}

// b45[j] = hb1[j] + sum_k mb4[k] * hw1[k,j]
__global__ void b45_kernel(const float* __restrict__ mb4, const float* __restrict__ hw1,
                           const float* __restrict__ hb1)
{
    int j = blockIdx.x * blockDim.x + threadIdx.x;
    if (j >= 384) return;
    float s = hb1[j];
    for (int k = 0; k < 768; k++) s += mb4[k] * hw1[(size_t)k * 384 + j];
    d_b45[j] = s;
}

// ---------------- Stage A (+ zero scores fused) ----------------
__global__ __launch_bounds__(128) void stage_a_kernel(
    const float* __restrict__ coords, const float* __restrict__ features,
    const float* __restrict__ times,
    const float* __restrict__ ln_g, const float* __restrict__ ln_b,
    const float* __restrict__ sw1, const float* __restrict__ sb1,
    const float* __restrict__ sw2, const float* __restrict__ sb2)
{
    __shared__ float s1[256], s2[4096], sb1s[64], sb2s[64], lg[4], lb[4];
    for (int t = threadIdx.x; t < 256; t += 128)  s1[t] = sw1[t];
    for (int t = threadIdx.x; t < 4096; t += 128) s2[t] = sw2[t];
    if (threadIdx.x < 64) { sb1s[threadIdx.x] = sb1[threadIdx.x]; sb2s[threadIdx.x] = sb2[threadIdx.x]; }
    if (threadIdx.x < 4)  { lg[threadIdx.x] = ln_g[threadIdx.x]; lb[threadIdx.x] = ln_b[threadIdx.x]; }
    __syncthreads();

    int i = blockIdx.x * 128 + threadIdx.x;
    d_scores[i] = 0.0f;

    float x0 = coords[i * 3 + 0], x1 = coords[i * 3 + 1], x2 = coords[i * 3 + 2], x3 = times[i];
    float mu = 0.25f * (x0 + x1 + x2 + x3);
    float e0 = x0 - mu, e1 = x1 - mu, e2 = x2 - mu, e3 = x3 - mu;
    float inv = 1.0f / sqrtf(0.25f * (e0*e0 + e1*e1 + e2*e2 + e3*e3) + 1e-5f);
    float xn0 = e0*inv*lg[0]+lb[0], xn1 = e1*inv*lg[1]+lb[1];
    float xn2 = e2*inv*lg[2]+lb[2], xn3 = e3*inv*lg[3]+lb[3];

    float t1[64];
#pragma unroll
    for (int j = 0; j < 64; j++) {
        float a = sb1s[j] + xn0*s1[j] + xn1*s1[64+j] + xn2*s1[128+j] + xn3*s1[192+j];
        t1[j] = fmaxf(a, 0.0f);
    }

    float*  hf = d_h0f + (size_t)i * 96;
    __half* hh = d_acth + HOFF_H0 + (size_t)i * 128;

#pragma unroll
    for (int c = 0; c < FEAT_DIM; c++) {
        float v = features[(size_t)i * FEAT_DIM + c];
        hf[c] = v; hh[c] = __float2half(v);
    }
    for (int j = 0; j < 64; j++) {
        float a = sb2s[j];
#pragma unroll
        for (int kk = 0; kk < 64; kk++) a += t1[kk] * s2[kk * 64 + j];
        a = fmaxf(a, 0.0f);
        hf[32 + j] = a; hh[32 + j] = __float2half(a);
    }
    __half z = __float2half(0.0f);
#pragma unroll
    for (int c = 96; c < 128; c++) hh[c] = z;
}

// ---------------- pass-1 fp16 HGEMM, k16-double-buffered fragments -----------
#define STAGES      4
#define STAGE_BYTES 16384
#define HG_SMEM     (STAGES * STAGE_BYTES)

// MODE: 0 = relu -> fp16 C; 2 = relu+score (no C write)
template <int MODE>
__global__ __launch_bounds__(128) void hgemm(
    const __half* __restrict__ A, const __half* __restrict__ B,
    const float* __restrict__ bias, __half* __restrict__ C,
    const float* __restrict__ hw2,
    int K, int Nn)
{
    extern __shared__ char smraw[];
    const uint32_t sb = smem_u32(smraw);
    const int tid = threadIdx.x;
    const int lane = tid & 31, wid = tid >> 5;
    const int wm = wid & 1, wn = wid >> 1;
    const int bm = blockIdx.y << 7, bn = blockIdx.x << 7;
    const int nIters = K >> 5;

    float acc[4][8][4];
#pragma unroll
    for (int a = 0; a < 4; a++)
#pragma unroll
        for (int b = 0; b < 8; b++)
#pragma unroll
            for (int c = 0; c < 4; c++) acc[a][b][c] = 0.0f;

    auto load_stage = [&](int s) {
        uint32_t base = sb + (uint32_t)(s % STAGES) * STAGE_BYTES;
        int k0 = s << 5;
#pragma unroll
        for (int t = 0; t < 8; t++) {
            int q = tid + (t << 7);
            int sec = q >> 9;
            int idx = q & 511;
            int row = idx >> 2;
            int c = idx & 3;
            uint32_t dst = base + (sec << 13) + row * 64 + ((c ^ ((row >> 1) & 3)) << 4);
            const __half* gp = (sec == 0)
                ? A + (size_t)(bm + row) * K + k0 + (c << 3)
                : B + (size_t)(bn + row) * K + k0 + (c << 3);
            CP_ASYNC16(dst, gp);
        }
    };

    uint32_t afA[4][4], bfA[8][2];   // fragment set A (k16=0 of current iter)
    uint32_t afB[4][4], bfB[8][2];   // fragment set B (k16=1 of current iter)

    auto load_frags = [&](uint32_t base, int k16, uint32_t af[4][4], uint32_t bfr[8][2]) {
#pragma unroll
        for (int mt = 0; mt < 4; mt++) {
            int row = (wm << 6) + (mt << 4) + (lane & 15);
            int ch = (k16 << 1) + (lane >> 4);
            uint32_t ad = base + row * 64 + ((ch ^ ((row >> 1) & 3)) << 4);
            LDMATRIX_X4(af[mt][0], af[mt][1], af[mt][2], af[mt][3], ad);
        }
#pragma unroll
        for (int pair = 0; pair < 4; pair++) {
            int row = (wn << 6) + (pair << 4) + (((lane >> 4) & 1) << 3) + (lane & 7);
            int ch = (k16 << 1) + ((lane >> 3) & 1);
            uint32_t ad = base + 8192 + row * 64 + ((ch ^ ((row >> 1) & 3)) << 4);
            uint32_t r0, r1, r2, r3;
            LDMATRIX_X4(r0, r1, r2, r3, ad);
            bfr[pair * 2][0] = r0;      bfr[pair * 2][1] = r1;
            bfr[pair * 2 + 1][0] = r2;  bfr[pair * 2 + 1][1] = r3;
        }
    };

    auto mma_all = [&](uint32_t af[4][4], uint32_t bfr[8][2]) {
#pragma unroll
        for (int mt = 0; mt < 4; mt++)
#pragma unroll
            for (int nt = 0; nt < 8; nt++)
                MMA16816(acc[mt][nt], af[mt], bfr[nt]);
    };

    // prologue: fill pipeline, first wait, preload fragA(it=0, k16=0)
#pragma unroll
    for (int s = 0; s < STAGES - 1; s++) {
        if (s < nIters) load_stage(s);
        CP_COMMIT();
    }
    CP_WAIT(STAGES - 2);
    __syncthreads();
    load_frags(sb, 0, afA, bfA);

    for (int it = 0; it < nIters; it++) {
        uint32_t base = sb + (uint32_t)(it % STAGES) * STAGE_BYTES;
        // load k16=1 fragments; overlaps with MMA(fragA) issue below
        load_frags(base, 1, afB, bfB);
        mma_all(afA, bfA);

        int nx = it + STAGES - 1;
        if (nx < nIters) load_stage(nx);
        CP_COMMIT();
        CP_WAIT(STAGES - 2);
        __syncthreads();

        // stage it+1 is complete at this point: prefetch its k16=0 fragments
        if (it + 1 < nIters) {
            uint32_t nbase = sb + (uint32_t)((it + 1) % STAGES) * STAGE_BYTES;
            load_frags(nbase, 0, afA, bfA);
        }
        mma_all(afB, bfB);
    }

    if (MODE == 2) {
#pragma unroll
        for (int mt = 0; mt < 4; mt++)
#pragma unroll
            for (int h = 0; h < 2; h++) {
                float s = 0.0f;
#pragma unroll
                for (int nt = 0; nt < 8; nt++) {
                    int c0 = bn + (wn << 6) + (nt << 3) + ((lane & 3) << 1);
                    float v0 = fmaxf(acc[mt][nt][h * 2 + 0] + bias[c0], 0.0f);
                    float v1 = fmaxf(acc[mt][nt][h * 2 + 1] + bias[c0 + 1], 0.0f);
                    s += v0 * hw2[c0] + v1 * hw2[c0 + 1];
                }
                s += __shfl_xor_sync(0xFFFFFFFFu, s, 1);
                s += __shfl_xor_sync(0xFFFFFFFFu, s, 2);
                if ((lane & 3) == 0) {
                    int R = bm + (wm << 6) + (mt << 4) + (lane >> 2) + h * 8;
                    atomicAdd(&d_scores[R], s);
                }
            }
        return;
    }

#pragma unroll
    for (int mt = 0; mt < 4; mt++)
#pragma unroll
        for (int nt = 0; nt < 8; nt++) {
            int r0 = bm + (wm << 6) + (mt << 4) + (lane >> 2);
            int c0 = bn + (wn << 6) + (nt << 3) + ((lane & 3) << 1);
            float2 bb = *(const float2*)&bias[c0];
#pragma unroll
            for (int h = 0; h < 2; h++) {
                int R = r0 + h * 8;
                float v0 = fmaxf(acc[mt][nt][h * 2 + 0] + bb.x, 0.0f);
                float v1 = fmaxf(acc[mt][nt][h * 2 + 1] + bb.y, 0.0f);
                *(__half2*)&C[(size_t)R * Nn + c0] =
                    __halves2half2(__float2half(v0), __float2half(v1));
            }
        }
}

// ---------------- fp32 SGEMM (validated, 128x128) ----------------
#define BM 128
#define BN 128
#define BKK 16
template <bool RELU>
__global__ __launch_bounds__(256) void sgemm_bias_kernel(
    const float* __restrict__ A, const float* __restrict__ W,
    const float* __restrict__ bias, float* __restrict__ C,
    int M, int K, int Nn)
{
    __shared__ float As[BKK][BM];
    __shared__ float Bs[BKK][BN];
    const int tid = threadIdx.x;
    const int bm = blockIdx.y * BM;
    const int bn = blockIdx.x * BN;
    const int tx = tid & 15;
    const int ty = tid >> 4;
    float acc[8][8];
#pragma unroll
    for (int i = 0; i < 8; i++)
#pragma unroll
        for (int j = 0; j < 8; j++) acc[i][j] = 0.0f;
    const int q0 = tid * 2;
    for (int k0 = 0; k0 < K; k0 += BKK) {
#pragma unroll
        for (int l = 0; l < 2; l++) {
            int q = q0 + l;
            int row = q >> 2;
            int col = (q & 3) * 4;
            float4 v = *(const float4*)&A[(size_t)(bm + row) * K + k0 + col];
            As[col + 0][row] = v.x; As[col + 1][row] = v.y;
            As[col + 2][row] = v.z; As[col + 3][row] = v.w;
        }
#pragma unroll
        for (int l = 0; l < 2; l++) {
            int q = q0 + l;
            int row = q >> 5;
            int col = (q & 31) * 4;
            *(float4*)&Bs[row][col] = *(const float4*)&W[(size_t)(k0 + row) * Nn + bn + col];
        }
        __syncthreads();
#pragma unroll
        for (int kk = 0; kk < BKK; kk++) {
            float a[8], b[8];
            float4 a0 = *(const float4*)&As[kk][ty * 8];
            float4 a1 = *(const float4*)&As[kk][ty * 8 + 4];
            a[0]=a0.x; a[1]=a0.y; a[2]=a0.z; a[3]=a0.w;
            a[4]=a1.x; a[5]=a1.y; a[6]=a1.z; a[7]=a1.w;
            float4 b0 = *(const float4*)&Bs[kk][tx * 8];
            float4 b1 = *(const float4*)&Bs[kk][tx * 8 + 4];
            b[0]=b0.x; b[1]=b0.y; b[2]=b0.z; b[3]=b0.w;
            b[4]=b1.x; b[5]=b1.y; b[6]=b1.z; b[7]=b1.w;
#pragma unroll
            for (int i = 0; i < 8; i++)
#pragma unroll
                for (int j = 0; j < 8; j++) acc[i][j] += a[i] * b[j];
        }
        __syncthreads();
    }
#pragma unroll
    for (int i = 0; i < 8; i++) {
        int row = bm + ty * 8 + i;
#pragma unroll
        for (int j = 0; j < 8; j += 4) {
            int col = bn + tx * 8 + j;
            float4 v;
            v.x = acc[i][j+0] + bias[col+0]; v.y = acc[i][j+1] + bias[col+1];
            v.z = acc[i][j+2] + bias[col+2]; v.w = acc[i][j+3] + bias[col+3];
            if (RELU) { v.x=fmaxf(v.x,0.f); v.y=fmaxf(v.y,0.f); v.z=fmaxf(v.z,0.f); v.w=fmaxf(v.w,0.f); }
            *(float4*)&C[(size_t)row * Nn + col] = v;
        }
    }
}

// ---------------- exact score for candidates ----------------
__global__ __launch_bounds__(256) void cscore_kernel(
    const float* __restrict__ hw2, const float* __restrict__ hb2)
{
    int gt = blockIdx.x * blockDim.x + threadIdx.x;
    int c = gt >> 5, lane = gt & 31;
    if (c >= CTOT) return;
    const float* row = d_cg + (size_t)c * 384;
    float s = 0.0f;
#pragma unroll
    for (int j = 0; j < 384; j += 32) s += row[j + lane] * hw2[j + lane];
#pragma unroll
    for (int o = 16; o > 0; o >>= 1) s += __shfl_down_sync(0xFFFFFFFFu, s, o);
    if (lane == 0) d_cscore[c] = s + hb2[0];
}

// ---------------- offsets ----------------
__global__ void offsets_kernel(const int* __restrict__ bids)
{
    int b = threadIdx.x;
    if (b > NBATCH) return;
    if (b == NBATCH) { d_off[NBATCH] = NPTS; return; }
    int lo = 0, hi = NPTS;
    while (lo < hi) { int mid = (lo + hi) >> 1; if (bids[mid] < b) lo = mid + 1; else hi = mid; }
    d_off[b] = lo;
}

__device__ __forceinline__ unsigned int ford(float f)
{
    unsigned int u = __float_as_uint(f);
    return (u & 0x80000000u) ? ~u : (u | 0x80000000u);
}

// ---------------- pass 1: approx top-CPB per batch (1024 threads) ------------
__global__ __launch_bounds__(1024) void topk1_kernel()
{
    __shared__ unsigned long long keys[SORT_N];
    int b = blockIdx.x;
    int base = d_off[b];
    int count = d_off[b + 1] - base;
    for (int t = threadIdx.x; t < SORT_N; t += 1024) {
        unsigned int ordv = (t < count) ? ford(d_scores[base + t]) : 0u;
        keys[t] = ((unsigned long long)ordv << 32) | (unsigned long long)(0xFFFFFFFFu - (unsigned)t);
    }
    __syncthreads();
    for (int k = 2; k <= SORT_N; k <<= 1)
        for (int j = k >> 1; j > 0; j >>= 1) {
            for (int t = threadIdx.x; t < SORT_N; t += 1024) {
                int ixj = t ^ j;
                if (ixj > t) {
                    unsigned long long a = keys[t], c = keys[ixj];
                    bool up = ((t & k) == 0);
                    if (up ? (a < c) : (a > c)) { keys[t] = c; keys[ixj] = a; }
                }
            }
            __syncthreads();
        }
    if (threadIdx.x < CPB) {
        unsigned int low = (unsigned int)(keys[threadIdx.x] & 0xFFFFFFFFu);
        d_cand[b * CPB + threadIdx.x] = (int)(0xFFFFFFFFu - low);
    }
}

// ---------------- gather candidate h0 (fp32) ----------------
__global__ __launch_bounds__(96) void gath0c_kernel()
{
    int c = blockIdx.x;
    int b = c / CPB;
    int pos = d_cand[c];
    int count = d_off[b + 1] - d_off[b];
    float v = 0.0f;
    if (pos < count) v = d_h0f[(size_t)(d_off[b] + pos) * 96 + threadIdx.x];
    d_c0[(size_t)c * 96 + threadIdx.x] = v;
}

// ---------------- pass 2: exact top-128 among CPB candidates ----------------
__global__ __launch_bounds__(256) void topk2_kernel()
{
    __shared__ unsigned long long keys[256];
    __shared__ int vals[256];
    int b = blockIdx.x;
    int count = d_off[b + 1] - d_off[b];
    int t = threadIdx.x;
    if (t < CPB) {
        int pos = d_cand[b * CPB + t];
        if (pos < count) {
            keys[t] = ((unsigned long long)ford(d_cscore[b * CPB + t]) << 32) |
                      (unsigned long long)(0xFFFFFFFFu - (unsigned)pos);
        } else {
            keys[t] = (unsigned long long)t;
        }
        vals[t] = t;
    } else {
        keys[t] = (unsigned long long)t;
        vals[t] = -1;
    }
    __syncthreads();
    for (int k = 2; k <= 256; k <<= 1)
        for (int j = k >> 1; j > 0; j >>= 1) {
            int ixj = t ^ j;
            if (ixj > t) {
                unsigned long long a = keys[t], c = keys[ixj];
                bool up = ((t & k) == 0);
                if (up ? (a < c) : (a > c)) {
                    keys[t] = c; keys[ixj] = a;
                    int va = vals[t]; vals[t] = vals[ixj]; vals[ixj] = va;
                }
            }
            __syncthreads();
        }
    if (t < MAX_TOKENS) {
        int jj = vals[t];
        d_fsel_j[b * MAX_TOKENS + t] = jj;
        d_fsel_p[b * MAX_TOKENS + t] = (jj >= 0) ? d_cand[b * CPB + jj] : 0x7FFFFFFF;
    }
}

// ---------------- gather outputs ----------------
__global__ __launch_bounds__(192) void gather_kernel(
    const float* __restrict__ coords, const float* __restrict__ times,
    float* __restrict__ out)
{
    int slot = blockIdx.x;
    int b = slot >> 7;
    int jj = d_fsel_j[slot];
    int pos = d_fsel_p[slot];
    int count = d_off[b + 1] - d_off[b];
    float* tok  = out + (size_t)slot * TOKEN_DIM;
    float* cent = out + TOK_ELEMS + (size_t)slot * 4;
    float* msk  = out + TOK_ELEMS + CENT_ELEMS + slot;
    if (jj >= 0 && pos < count) {
        int i = d_off[b] + pos;
        const float* src = d_cpf + (size_t)(b * CPB + jj) * TOKEN_DIM;
        for (int j = threadIdx.x; j < TOKEN_DIM / 4; j += blockDim.x)
            ((float4*)tok)[j] = ((const float4*)src)[j];
        if (threadIdx.x < 3) cent[threadIdx.x] = coords[(size_t)i * 3 + threadIdx.x];
        if (threadIdx.x == 3) cent[3] = times[i];
        if (threadIdx.x == 0) *msk = 1.0f;
    } else {
        for (int j = threadIdx.x; j < TOKEN_DIM; j += blockDim.x) tok[j] = 0.0f;
        if (threadIdx.x < 4) cent[threadIdx.x] = 0.0f;
        if (threadIdx.x == 0) *msk = 0.0f;
    }
}

// ---------------- launch ----------------
extern "C" void kernel_launch(void* const* d_in, const int* in_sizes, int n_in,
                              void* d_out, int out_size)
{
    const float* coords   = (const float*)d_in[0];
    const float* features = (const float*)d_in[1];
    const float* times    = (const float*)d_in[2];
    const int*   bids     = (const int*)d_in[3];
    const float* ln_g = (const float*)d_in[4];
    const float* ln_b = (const float*)d_in[5];
    const float* sw1 = (const float*)d_in[6];
    const float* sb1 = (const float*)d_in[7];
    const float* sw2 = (const float*)d_in[8];
    const float* sb2 = (const float*)d_in[9];
    const float* mw1 = (const float*)d_in[10];
    const float* mb1 = (const float*)d_in[11];
    const float* mw2 = (const float*)d_in[12];
    const float* mb2 = (const float*)d_in[13];
    const float* mw3 = (const float*)d_in[14];
    const float* mb3 = (const float*)d_in[15];
    const float* mw4 = (const float*)d_in[16];
    const float* mb4 = (const float*)d_in[17];
    const float* hw1 = (const float*)d_in[18];
    const float* hb1 = (const float*)d_in[19];
    const float* hw2 = (const float*)d_in[20];
    const float* hb2 = (const float*)d_in[21];

    cudaFuncSetAttribute(hgemm<0>, cudaFuncAttributeMaxDynamicSharedMemorySize, HG_SMEM);
    cudaFuncSetAttribute(hgemm<2>, cudaFuncAttributeMaxDynamicSharedMemorySize, HG_SMEM);

    __half *acth, *wth;
    float *c0, *c1, *c2, *c3, *cpf, *cg, *w45f, *b45p, *zeros;
    cudaGetSymbolAddress((void**)&acth, d_acth);
    cudaGetSymbolAddress((void**)&wth,  d_wth);
    cudaGetSymbolAddress((void**)&c0,  d_c0);
    cudaGetSymbolAddress((void**)&c1,  d_c1);
    cudaGetSymbolAddress((void**)&c2,  d_c2);
    cudaGetSymbolAddress((void**)&c3,  d_c3);
    cudaGetSymbolAddress((void**)&cpf, d_cpf);
    cudaGetSymbolAddress((void**)&cg,  d_cg);
    cudaGetSymbolAddress((void**)&w45f, d_w45f);
    cudaGetSymbolAddress((void**)&b45p, d_b45);
    cudaGetSymbolAddress((void**)&zeros, d_zero384);
    float* out = (float*)d_out;

    wsplit_all<<<(1146880 + 255) / 256, 256>>>(mw1, mw2, mw3, mw4);                                   // 1
    stage_a_kernel<<<NPTS / 128, 128>>>(coords, features, times, ln_g, ln_b, sw1, sb1, sw2, sb2);     // 2
    hgemm<0><<<dim3(2, NPTS / 128), 128, HG_SMEM>>>(acth + HOFF_H0, wth + WOFF_1, mb1, acth + HOFF_H1, nullptr, 128, 256); // 3
    hgemm<0><<<dim3(4, NPTS / 128), 128, HG_SMEM>>>(acth + HOFF_H1, wth + WOFF_2, mb2, acth + HOFF_H2, nullptr, 256, 512); // 4
    sgemm_bias_kernel<false><<<dim3(384 / BN, 768 / BM), 256>>>(mw4, hw1, zeros, w45f, 768, 768, 384); // 5
    hgemm<0><<<dim3(6, NPTS / 128), 128, HG_SMEM>>>(acth + HOFF_H2, wth + WOFF_3, mb3, acth + HOFF_H3, nullptr, 512, 768); // 6 <- ncu (L3)
    b45_kernel<<<2, 192>>>(mb4, hw1, hb1);                                                            // 7
    wsplit_h<<<(384 * 768 + 255) / 256, 256>>>(w45f, wth + WOFF_5, 768, 768, 384);                    // 8
    hgemm<2><<<dim3(3, NPTS / 128), 128, HG_SMEM>>>(acth + HOFF_H3, wth + WOFF_5, b45p, nullptr, hw2, 768, 384); // 9
    offsets_kernel<<<1, 128>>>(bids);                                                                 // 10

    topk1_kernel<<<NBATCH, 1024>>>();
    gath0c_kernel<<<CTOT, 96>>>();

    // pass 2: exact fp32 chain on candidates (validated 128x128 tiles; full L4+L5)
    sgemm_bias_kernel<true ><<<dim3(256 / BN, CTOT / BM), 256>>>(c0,  mw1, mb1, c1,  CTOT,  96, 256);
    sgemm_bias_kernel<true ><<<dim3(512 / BN, CTOT / BM), 256>>>(c1,  mw2, mb2, c2,  CTOT, 256, 512);
    sgemm_bias_kernel<true ><<<dim3(768 / BN, CTOT / BM), 256>>>(c2,  mw3, mb3, c3,  CTOT, 512, 768);
    sgemm_bias_kernel<false><<<dim3(768 / BN, CTOT / BM), 256>>>(c3,  mw4, mb4, cpf, CTOT, 768, 768);
    sgemm_bias_kernel<true ><<<dim3(384 / BN, CTOT / BM), 256>>>(cpf, hw1, hb1, cg,  CTOT, 768, 384);
    cscore_kernel<<<(CTOT * 32 + 255) / 256, 256>>>(hw2, hb2);

    topk2_kernel<<<NBATCH, 256>>>();
    gather_kernel<<<NBATCH * MAX_TOKENS, 192>>>(coords, times, out);
}

// round 16
// speedup vs baseline: 1.1631x; 1.0369x over previous
#include <cuda_runtime.h>
#include <cuda_fp16.h>
#include <math.h>
#include <stdint.h>

#define NPTS        131072
#define NBATCH      64
#define FEAT_DIM    32
#define TOKEN_DIM   768
#define MAX_TOKENS  128
#define SORT_N      4096
#define CPB         144
#define CTOT        (NBATCH * CPB)            // 9216
#define TOK_ELEMS   (NBATCH * MAX_TOKENS * TOKEN_DIM)
#define CENT_ELEMS  (NBATCH * MAX_TOKENS * 4)

// ---------------- Scratch arenas ----------------
#define HOFF_H0 0ULL
#define HOFF_H1 16777216ULL
#define HOFF_H2 50331648ULL
#define HOFF_H3 117440512ULL
#define ACTH_TOT 218103808ULL
__device__ __half d_acth[ACTH_TOT];

#define WOFF_1 0ULL
#define WOFF_2 32768ULL
#define WOFF_3 163840ULL
#define WOFF_4 557056ULL
#define WOFF_5 1146880ULL          // fused W45 (384 x 768)
#define WTH_TOT 1441792ULL
__device__ __half d_wth[WTH_TOT];

__device__ float d_h0f[(size_t)NPTS * 96];

__device__ float d_w45f[768 * 384];
__device__ float d_b45[384];
__device__ float d_zero384[384];

__device__ float d_c0 [(size_t)CTOT * 96];
__device__ float d_c1 [(size_t)CTOT * 256];
__device__ float d_c2 [(size_t)CTOT * 512];
__device__ float d_c3 [(size_t)CTOT * 768];
__device__ float d_cpf[(size_t)CTOT * 768];
__device__ float d_cg [(size_t)CTOT * 384];

__device__ float d_scores[NPTS];
__device__ float d_cscore[CTOT];
__device__ int   d_off[NBATCH + 1];
__device__ int   d_cand[CTOT];
__device__ int   d_fsel_j[NBATCH * MAX_TOKENS];
__device__ int   d_fsel_p[NBATCH * MAX_TOKENS];

// ---------------- PTX helpers ----------------
__device__ __forceinline__ uint32_t smem_u32(const void* p) {
    uint32_t a;
    asm("{ .reg .u64 t; cvta.to.shared.u64 t, %1; cvt.u32.u64 %0, t; }" : "=r"(a) : "l"(p));
    return a;
}
#define CP_ASYNC16(dst, src) \
    asm volatile("cp.async.cg.shared.global [%0], [%1], 16;" :: "r"(dst), "l"(src))
#define CP_COMMIT() asm volatile("cp.async.commit_group;")
#define CP_WAIT(n)  asm volatile("cp.async.wait_group %0;" :: "n"(n))
#define LDMATRIX_X4(r0, r1, r2, r3, addr) \
    asm volatile("ldmatrix.sync.aligned.m8n8.x4.shared.b16 {%0,%1,%2,%3}, [%4];" \
        : "=r"(r0), "=r"(r1), "=r"(r2), "=r"(r3) : "r"(addr))
#define MMA16816(d, a, b) \
    asm volatile("mma.sync.aligned.m16n8k16.row.col.f32.f16.f16.f32 " \
        "{%0,%1,%2,%3}, {%4,%5,%6,%7}, {%8,%9}, {%0,%1,%2,%3};" \
        : "+f"((d)[0]), "+f"((d)[1]), "+f"((d)[2]), "+f"((d)[3]) \
        : "r"((a)[0]), "r"((a)[1]), "r"((a)[2]), "r"((a)[3]), \
          "r"((b)[0]), "r"((b)[1]))

// ---------------- fused prep: stage_a (blocks 0..1023) + wsplit (rest) -------
#define WSPLIT_ELEMS 1146880
#define PREP_GRID (1024 + (WSPLIT_ELEMS + 127) / 128)   // 1024 + 8960

__global__ __launch_bounds__(128) void prep_kernel(
    const float* __restrict__ coords, const float* __restrict__ features,
    const float* __restrict__ times,
    const float* __restrict__ ln_g, const float* __restrict__ ln_b,
    const float* __restrict__ sw1, const float* __restrict__ sb1,
    const float* __restrict__ sw2, const float* __restrict__ sb2,
    const float* __restrict__ W1, const float* __restrict__ W2,
    const float* __restrict__ W3, const float* __restrict__ W4)
{
    if (blockIdx.x >= 1024) {
        int idx = (blockIdx.x - 1024) * 128 + threadIdx.x;
        if (idx >= WSPLIT_ELEMS) return;
        const float* W; __half* t; int K, Kpad, Nn;
        if (idx < 32768)        { W = W1; t = d_wth + WOFF_1; K =  96; Kpad = 128; Nn = 256; }
        else if (idx < 163840)  { W = W2; t = d_wth + WOFF_2; K = 256; Kpad = 256; Nn = 512; idx -= 32768; }
        else if (idx < 557056)  { W = W3; t = d_wth + WOFF_3; K = 512; Kpad = 512; Nn = 768; idx -= 163840; }
        else                    { W = W4; t = d_wth + WOFF_4; K = 768; Kpad = 768; Nn = 768; idx -= 557056; }
        int n = idx / Kpad, k = idx - n * Kpad;
        t[idx] = __float2half((k < K) ? W[(size_t)k * Nn + n] : 0.0f);
        return;
    }

    __shared__ float s1[256], s2[4096], sb1s[64], sb2s[64], lg[4], lb[4];
    for (int t = threadIdx.x; t < 256; t += 128)  s1[t] = sw1[t];
    for (int t = threadIdx.x; t < 4096; t += 128) s2[t] = sw2[t];
    if (threadIdx.x < 64) { sb1s[threadIdx.x] = sb1[threadIdx.x]; sb2s[threadIdx.x] = sb2[threadIdx.x]; }
    if (threadIdx.x < 4)  { lg[threadIdx.x] = ln_g[threadIdx.x]; lb[threadIdx.x] = ln_b[threadIdx.x]; }
    __syncthreads();

    int i = blockIdx.x * 128 + threadIdx.x;
    d_scores[i] = 0.0f;

    float x0 = coords[i * 3 + 0], x1 = coords[i * 3 + 1], x2 = coords[i * 3 + 2], x3 = times[i];
    float mu = 0.25f * (x0 + x1 + x2 + x3);
    float e0 = x0 - mu, e1 = x1 - mu, e2 = x2 - mu, e3 = x3 - mu;
    float inv = 1.0f / sqrtf(0.25f * (e0*e0 + e1*e1 + e2*e2 + e3*e3) + 1e-5f);
    float xn0 = e0*inv*lg[0]+lb[0], xn1 = e1*inv*lg[1]+lb[1];
    float xn2 = e2*inv*lg[2]+lb[2], xn3 = e3*inv*lg[3]+lb[3];

    float t1[64];
#pragma unroll
    for (int j = 0; j < 64; j++) {
        float a = sb1s[j] + xn0*s1[j] + xn1*s1[64+j] + xn2*s1[128+j] + xn3*s1[192+j];
        t1[j] = fmaxf(a, 0.0f);
    }

    float*  hf = d_h0f + (size_t)i * 96;
    __half* hh = d_acth + HOFF_H0 + (size_t)i * 128;

#pragma unroll
    for (int c = 0; c < FEAT_DIM; c++) {
        float v = features[(size_t)i * FEAT_DIM + c];
        hf[c] = v; hh[c] = __float2half(v);
    }
    for (int j = 0; j < 64; j++) {
        float a = sb2s[j];
#pragma unroll
        for (int kk = 0; kk < 64; kk++) a += t1[kk] * s2[kk * 64 + j];
        a = fmaxf(a, 0.0f);
        hf[32 + j] = a; hh[32 + j] = __float2half(a);
    }
    __half z = __float2half(0.0f);
#pragma unroll
    for (int c = 96; c < 128; c++) hh[c] = z;
}

__global__ void wsplit_h(const float* __restrict__ W, __half* __restrict__ t,
                         int K, int Kpad, int Nn)
{
    int idx = blockIdx.x * blockDim.x + threadIdx.x;
    if (idx >= Nn * Kpad) return;
    int n = idx / Kpad, k = idx - n * Kpad;
    t[idx] = __float2half((k < K) ? W[(size_t)k * Nn + n] : 0.0f);
}

__global__ void b45_kernel(const float* __restrict__ mb4, const float* __restrict__ hw1,
                           const float* __restrict__ hb1)
{
    int j = blockIdx.x * blockDim.x + threadIdx.x;
    if (j >= 384) return;
    float s = hb1[j];
    for (int k = 0; k < 768; k++) s += mb4[k] * hw1[(size_t)k * 384 + j];
    d_b45[j] = s;
}

// ---------------- pass-1 fp16 HGEMM, BK=64, 3 stages, frag ping-pong ---------
#define STAGES      3
#define STAGE_BYTES 32768
#define HG_SMEM     (STAGES * STAGE_BYTES)

// MODE: 0 = relu -> fp16 C; 2 = relu+score (no C write)
template <int MODE>
__global__ __launch_bounds__(128) void hgemm(
    const __half* __restrict__ A, const __half* __restrict__ B,
    const float* __restrict__ bias, __half* __restrict__ C,
    const float* __restrict__ hw2,
    int K, int Nn)
{
    extern __shared__ char smraw[];
    const uint32_t sb = smem_u32(smraw);
    const int tid = threadIdx.x;
    const int lane = tid & 31, wid = tid >> 5;
    const int wm = wid & 1, wn = wid >> 1;
    const int bm = blockIdx.y << 7, bn = blockIdx.x << 7;
    const int nIters = K >> 6;

    float acc[4][8][4];
#pragma unroll
    for (int a = 0; a < 4; a++)
#pragma unroll
        for (int b = 0; b < 8; b++)
#pragma unroll
            for (int c = 0; c < 4; c++) acc[a][b][c] = 0.0f;

    // stage: A 128x64 fp16 (128B rows, 8 chunks) + B 128x64. swizzle c^(row&7).
    auto load_stage = [&](int s) {
        uint32_t base = sb + (uint32_t)(s % STAGES) * STAGE_BYTES;
        int k0 = s << 6;
#pragma unroll
        for (int t = 0; t < 16; t++) {
            int q = tid + (t << 7);          // 0..2047
            int sec = q >> 10;               // 0:A 1:B
            int idx = q & 1023;
            int row = idx >> 3;              // 0..127
            int c = idx & 7;                 // 0..7
            uint32_t dst = base + (sec << 14) + row * 128 + ((c ^ (row & 7)) << 4);
            const __half* gp = (sec == 0)
                ? A + (size_t)(bm + row) * K + k0 + (c << 3)
                : B + (size_t)(bn + row) * K + k0 + (c << 3);
            CP_ASYNC16(dst, gp);
        }
    };

    uint32_t afA[4][4], bfA[8][2];   // ping
    uint32_t afB[4][4], bfB[8][2];   // pong

    auto load_frags = [&](uint32_t base, int p, uint32_t af[4][4], uint32_t bfr[8][2]) {
#pragma unroll
        for (int mt = 0; mt < 4; mt++) {
            int row = (wm << 6) + (mt << 4) + (lane & 15);
            int ch = (p << 1) + (lane >> 4);
            uint32_t ad = base + row * 128 + ((ch ^ (row & 7)) << 4);
            LDMATRIX_X4(af[mt][0], af[mt][1], af[mt][2], af[mt][3], ad);
        }
#pragma unroll
        for (int pair = 0; pair < 4; pair++) {
            int row = (wn << 6) + (pair << 4) + (((lane >> 4) & 1) << 3) + (lane & 7);
            int ch = (p << 1) + ((lane >> 3) & 1);
            uint32_t ad = base + 16384 + row * 128 + ((ch ^ (row & 7)) << 4);
            uint32_t r0, r1, r2, r3;
            LDMATRIX_X4(r0, r1, r2, r3, ad);
            bfr[pair * 2][0] = r0;      bfr[pair * 2][1] = r1;
            bfr[pair * 2 + 1][0] = r2;  bfr[pair * 2 + 1][1] = r3;
        }
    };

    auto mma_all = [&](uint32_t af[4][4], uint32_t bfr[8][2]) {
#pragma unroll
        for (int mt = 0; mt < 4; mt++)
#pragma unroll
            for (int nt = 0; nt < 8; nt++)
                MMA16816(acc[mt][nt], af[mt], bfr[nt]);
    };

    // prologue
#pragma unroll
    for (int s = 0; s < STAGES - 1; s++) {
        if (s < nIters) load_stage(s);
        CP_COMMIT();
    }
    CP_WAIT(STAGES - 2);
    __syncthreads();
    load_frags(sb, 0, afA, bfA);

    for (int it = 0; it < nIters; it++) {
        uint32_t base = sb + (uint32_t)(it % STAGES) * STAGE_BYTES;
        // phases 1..3 ping-pong against MMA of previous phase
        load_frags(base, 1, afB, bfB);
        mma_all(afA, bfA);                       // phase 0
        load_frags(base, 2, afA, bfA);
        mma_all(afB, bfB);                       // phase 1
        load_frags(base, 3, afB, bfB);
        mma_all(afA, bfA);                       // phase 2

        int nx = it + STAGES - 1;
        if (nx < nIters) load_stage(nx);
        CP_COMMIT();
        CP_WAIT(STAGES - 2);
        __syncthreads();

        if (it + 1 < nIters) {
            uint32_t nbase = sb + (uint32_t)((it + 1) % STAGES) * STAGE_BYTES;
            load_frags(nbase, 0, afA, bfA);
        }
        mma_all(afB, bfB);                       // phase 3
    }

    if (MODE == 2) {
#pragma unroll
        for (int mt = 0; mt < 4; mt++)
#pragma unroll
            for (int h = 0; h < 2; h++) {
                float s = 0.0f;
#pragma unroll
                for (int nt = 0; nt < 8; nt++) {
                    int c0 = bn + (wn << 6) + (nt << 3) + ((lane & 3) << 1);
                    float v0 = fmaxf(acc[mt][nt][h * 2 + 0] + bias[c0], 0.0f);
                    float v1 = fmaxf(acc[mt][nt][h * 2 + 1] + bias[c0 + 1], 0.0f);
                    s += v0 * hw2[c0] + v1 * hw2[c0 + 1];
                }
                s += __shfl_xor_sync(0xFFFFFFFFu, s, 1);
                s += __shfl_xor_sync(0xFFFFFFFFu, s, 2);
                if ((lane & 3) == 0) {
                    int R = bm + (wm << 6) + (mt << 4) + (lane >> 2) + h * 8;
                    atomicAdd(&d_scores[R], s);
                }
            }
        return;
    }

#pragma unroll
    for (int mt = 0; mt < 4; mt++)
#pragma unroll
        for (int nt = 0; nt < 8; nt++) {
            int r0 = bm + (wm << 6) + (mt << 4) + (lane >> 2);
            int c0 = bn + (wn << 6) + (nt << 3) + ((lane & 3) << 1);
            float2 bb = *(const float2*)&bias[c0];
#pragma unroll
            for (int h = 0; h < 2; h++) {
                int R = r0 + h * 8;
                float v0 = fmaxf(acc[mt][nt][h * 2 + 0] + bb.x, 0.0f);
                float v1 = fmaxf(acc[mt][nt][h * 2 + 1] + bb.y, 0.0f);
                *(__half2*)&C[(size_t)R * Nn + c0] =
                    __halves2half2(__float2half(v0), __float2half(v1));
            }
        }
}

// ---------------- fp32 SGEMM (validated, 128x128) ----------------
#define BM 128
#define BN 128
#define BKK 16
template <bool RELU>
__global__ __launch_bounds__(256) void sgemm_bias_kernel(
    const float* __restrict__ A, const float* __restrict__ W,
    const float* __restrict__ bias, float* __restrict__ C,
    int M, int K, int Nn)
{
    __shared__ float As[BKK][BM];
    __shared__ float Bs[BKK][BN];
    const int tid = threadIdx.x;
    const int bm = blockIdx.y * BM;
    const int bn = blockIdx.x * BN;
    const int tx = tid & 15;
    const int ty = tid >> 4;
    float acc[8][8];
#pragma unroll
    for (int i = 0; i < 8; i++)
#pragma unroll
        for (int j = 0; j < 8; j++) acc[i][j] = 0.0f;
    const int q0 = tid * 2;
    for (int k0 = 0; k0 < K; k0 += BKK) {
#pragma unroll
        for (int l = 0; l < 2; l++) {
            int q = q0 + l;
            int row = q >> 2;
            int col = (q & 3) * 4;
            float4 v = *(const float4*)&A[(size_t)(bm + row) * K + k0 + col];
            As[col + 0][row] = v.x; As[col + 1][row] = v.y;
            As[col + 2][row] = v.z; As[col + 3][row] = v.w;
        }
#pragma unroll
        for (int l = 0; l < 2; l++) {
            int q = q0 + l;
            int row = q >> 5;
            int col = (q & 31) * 4;
            *(float4*)&Bs[row][col] = *(const float4*)&W[(size_t)(k0 + row) * Nn + bn + col];
        }
        __syncthreads();
#pragma unroll
        for (int kk = 0; kk < BKK; kk++) {
            float a[8], b[8];
            float4 a0 = *(const float4*)&As[kk][ty * 8];
            float4 a1 = *(const float4*)&As[kk][ty * 8 + 4];
            a[0]=a0.x; a[1]=a0.y; a[2]=a0.z; a[3]=a0.w;
            a[4]=a1.x; a[5]=a1.y; a[6]=a1.z; a[7]=a1.w;
            float4 b0 = *(const float4*)&Bs[kk][tx * 8];
            float4 b1 = *(const float4*)&Bs[kk][tx * 8 + 4];
            b[0]=b0.x; b[1]=b0.y; b[2]=b0.z; b[3]=b0.w;
            b[4]=b1.x; b[5]=b1.y; b[6]=b1.z; b[7]=b1.w;
#pragma unroll
            for (int i = 0; i < 8; i++)
#pragma unroll
                for (int j = 0; j < 8; j++) acc[i][j] += a[i] * b[j];
        }
        __syncthreads();
    }
#pragma unroll
    for (int i = 0; i < 8; i++) {
        int row = bm + ty * 8 + i;
#pragma unroll
        for (int j = 0; j < 8; j += 4) {
            int col = bn + tx * 8 + j;
            float4 v;
            v.x = acc[i][j+0] + bias[col+0]; v.y = acc[i][j+1] + bias[col+1];
            v.z = acc[i][j+2] + bias[col+2]; v.w = acc[i][j+3] + bias[col+3];
            if (RELU) { v.x=fmaxf(v.x,0.f); v.y=fmaxf(v.y,0.f); v.z=fmaxf(v.z,0.f); v.w=fmaxf(v.w,0.f); }
            *(float4*)&C[(size_t)row * Nn + col] = v;
        }
    }
}

// ---------------- exact score for candidates ----------------
__global__ __launch_bounds__(256) void cscore_kernel(
    const float* __restrict__ hw2, const float* __restrict__ hb2)
{
    int gt = blockIdx.x * blockDim.x + threadIdx.x;
    int c = gt >> 5, lane = gt & 31;
    if (c >= CTOT) return;
    const float* row = d_cg + (size_t)c * 384;
    float s = 0.0f;
#pragma unroll
    for (int j = 0; j < 384; j += 32) s += row[j + lane] * hw2[j + lane];
#pragma unroll
    for (int o = 16; o > 0; o >>= 1) s += __shfl_down_sync(0xFFFFFFFFu, s, o);
    if (lane == 0) d_cscore[c] = s + hb2[0];
}

// ---------------- offsets ----------------
__global__ void offsets_kernel(const int* __restrict__ bids)
{
    int b = threadIdx.x;
    if (b > NBATCH) return;
    if (b == NBATCH) { d_off[NBATCH] = NPTS; return; }
    int lo = 0, hi = NPTS;
    while (lo < hi) { int mid = (lo + hi) >> 1; if (bids[mid] < b) lo = mid + 1; else hi = mid; }
    d_off[b] = lo;
}

__device__ __forceinline__ unsigned int ford(float f)
{
    unsigned int u = __float_as_uint(f);
    return (u & 0x80000000u) ? ~u : (u | 0x80000000u);
}

// ---------------- pass 1: approx top-CPB per batch ----------------
__global__ __launch_bounds__(1024) void topk1_kernel()
{
    __shared__ unsigned long long keys[SORT_N];
    int b = blockIdx.x;
    int base = d_off[b];
    int count = d_off[b + 1] - base;
    for (int t = threadIdx.x; t < SORT_N; t += 1024) {
        unsigned int ordv = (t < count) ? ford(d_scores[base + t]) : 0u;
        keys[t] = ((unsigned long long)ordv << 32) | (unsigned long long)(0xFFFFFFFFu - (unsigned)t);
    }
    __syncthreads();
    for (int k = 2; k <= SORT_N; k <<= 1)
        for (int j = k >> 1; j > 0; j >>= 1) {
            for (int t = threadIdx.x; t < SORT_N; t += 1024) {
                int ixj = t ^ j;
                if (ixj > t) {
                    unsigned long long a = keys[t], c = keys[ixj];
                    bool up = ((t & k) == 0);
                    if (up ? (a < c) : (a > c)) { keys[t] = c; keys[ixj] = a; }
                }
            }
            __syncthreads();
        }
    if (threadIdx.x < CPB) {
        unsigned int low = (unsigned int)(keys[threadIdx.x] & 0xFFFFFFFFu);
        d_cand[b * CPB + threadIdx.x] = (int)(0xFFFFFFFFu - low);
    }
}

// ---------------- gather candidate h0 (fp32) ----------------
__global__ __launch_bounds__(96) void gath0c_kernel()
{
    int c = blockIdx.x;
    int b = c / CPB;
    int pos = d_cand[c];
    int count = d_off[b + 1] - d_off[b];
    float v = 0.0f;
    if (pos < count) v = d_h0f[(size_t)(d_off[b] + pos) * 96 + threadIdx.x];
    d_c0[(size_t)c * 96 + threadIdx.x] = v;
}

// ---------------- pass 2: exact top-128 among CPB candidates ----------------
__global__ __launch_bounds__(256) void topk2_kernel()
{
    __shared__ unsigned long long keys[256];
    __shared__ int vals[256];
    int b = blockIdx.x;
    int count = d_off[b + 1] - d_off[b];
    int t = threadIdx.x;
    if (t < CPB) {
        int pos = d_cand[b * CPB + t];
        if (pos < count) {
            keys[t] = ((unsigned long long)ford(d_cscore[b * CPB + t]) << 32) |
                      (unsigned long long)(0xFFFFFFFFu - (unsigned)pos);
        } else {
            keys[t] = (unsigned long long)t;
        }
        vals[t] = t;
    } else {
        keys[t] = (unsigned long long)t;
        vals[t] = -1;
    }
    __syncthreads();
    for (int k = 2; k <= 256; k <<= 1)
        for (int j = k >> 1; j > 0; j >>= 1) {
            int ixj = t ^ j;
            if (ixj > t) {
                unsigned long long a = keys[t], c = keys[ixj];
                bool up = ((t & k) == 0);
                if (up ? (a < c) : (a > c)) {
                    keys[t] = c; keys[ixj] = a;
                    int va = vals[t]; vals[t] = vals[ixj]; vals[ixj] = va;
                }
            }
            __syncthreads();
        }
    if (t < MAX_TOKENS) {
        int jj = vals[t];
        d_fsel_j[b * MAX_TOKENS + t] = jj;
        d_fsel_p[b * MAX_TOKENS + t] = (jj >= 0) ? d_cand[b * CPB + jj] : 0x7FFFFFFF;
    }
}

// ---------------- gather outputs ----------------
__global__ __launch_bounds__(192) void gather_kernel(
    const float* __restrict__ coords, const float* __restrict__ times,
    float* __restrict__ out)
{
    int slot = blockIdx.x;
    int b = slot >> 7;
    int jj = d_fsel_j[slot];
    int pos = d_fsel_p[slot];
    int count = d_off[b + 1] - d_off[b];
    float* tok  = out + (size_t)slot * TOKEN_DIM;
    float* cent = out + TOK_ELEMS + (size_t)slot * 4;
    float* msk  = out + TOK_ELEMS + CENT_ELEMS + slot;
    if (jj >= 0 && pos < count) {
        int i = d_off[b] + pos;
        const float* src = d_cpf + (size_t)(b * CPB + jj) * TOKEN_DIM;
        for (int j = threadIdx.x; j < TOKEN_DIM / 4; j += blockDim.x)
            ((float4*)tok)[j] = ((const float4*)src)[j];
        if (threadIdx.x < 3) cent[threadIdx.x] = coords[(size_t)i * 3 + threadIdx.x];
        if (threadIdx.x == 3) cent[3] = times[i];
        if (threadIdx.x == 0) *msk = 1.0f;
    } else {
        for (int j = threadIdx.x; j < TOKEN_DIM; j += blockDim.x) tok[j] = 0.0f;
        if (threadIdx.x < 4) cent[threadIdx.x] = 0.0f;
        if (threadIdx.x == 0) *msk = 0.0f;
    }
}

// ---------------- launch ----------------
extern "C" void kernel_launch(void* const* d_in, const int* in_sizes, int n_in,
                              void* d_out, int out_size)
{
    const float* coords   = (const float*)d_in[0];
    const float* features = (const float*)d_in[1];
    const float* times    = (const float*)d_in[2];
    const int*   bids     = (const int*)d_in[3];
    const float* ln_g = (const float*)d_in[4];
    const float* ln_b = (const float*)d_in[5];
    const float* sw1 = (const float*)d_in[6];
    const float* sb1 = (const float*)d_in[7];
    const float* sw2 = (const float*)d_in[8];
    const float* sb2 = (const float*)d_in[9];
    const float* mw1 = (const float*)d_in[10];
    const float* mb1 = (const float*)d_in[11];
    const float* mw2 = (const float*)d_in[12];
    const float* mb2 = (const float*)d_in[13];
    const float* mw3 = (const float*)d_in[14];
    const float* mb3 = (const float*)d_in[15];
    const float* mw4 = (const float*)d_in[16];
    const float* mb4 = (const float*)d_in[17];
    const float* hw1 = (const float*)d_in[18];
    const float* hb1 = (const float*)d_in[19];
    const float* hw2 = (const float*)d_in[20];
    const float* hb2 = (const float*)d_in[21];

    cudaFuncSetAttribute(hgemm<0>, cudaFuncAttributeMaxDynamicSharedMemorySize, HG_SMEM);
    cudaFuncSetAttribute(hgemm<2>, cudaFuncAttributeMaxDynamicSharedMemorySize, HG_SMEM);

    __half *acth, *wth;
    float *c0, *c1, *c2, *c3, *cpf, *cg, *w45f, *b45p, *zeros;
    cudaGetSymbolAddress((void**)&acth, d_acth);
    cudaGetSymbolAddress((void**)&wth,  d_wth);
    cudaGetSymbolAddress((void**)&c0,  d_c0);
    cudaGetSymbolAddress((void**)&c1,  d_c1);
    cudaGetSymbolAddress((void**)&c2,  d_c2);
    cudaGetSymbolAddress((void**)&c3,  d_c3);
    cudaGetSymbolAddress((void**)&cpf, d_cpf);
    cudaGetSymbolAddress((void**)&cg,  d_cg);
    cudaGetSymbolAddress((void**)&w45f, d_w45f);
    cudaGetSymbolAddress((void**)&b45p, d_b45);
    cudaGetSymbolAddress((void**)&zeros, d_zero384);
    float* out = (float*)d_out;

    // Launch order: empirically ncu captures the 4th launch -> L3 (K=512).
    prep_kernel<<<PREP_GRID, 128>>>(coords, features, times, ln_g, ln_b, sw1, sb1, sw2, sb2,
                                    mw1, mw2, mw3, mw4);                                       // 1
    hgemm<0><<<dim3(2, NPTS / 128), 128, HG_SMEM>>>(acth + HOFF_H0, wth + WOFF_1, mb1, acth + HOFF_H1, nullptr, 128, 256); // 2
    hgemm<0><<<dim3(4, NPTS / 128), 128, HG_SMEM>>>(acth + HOFF_H1, wth + WOFF_2, mb2, acth + HOFF_H2, nullptr, 256, 512); // 3
    hgemm<0><<<dim3(6, NPTS / 128), 128, HG_SMEM>>>(acth + HOFF_H2, wth + WOFF_3, mb3, acth + HOFF_H3, nullptr, 512, 768); // 4 <- ncu (L3)
    sgemm_bias_kernel<false><<<dim3(384 / BN, 768 / BM), 256>>>(mw4, hw1, zeros, w45f, 768, 768, 384); // 5
    b45_kernel<<<2, 192>>>(mb4, hw1, hb1);                                                     // 6
    wsplit_h<<<(384 * 768 + 255) / 256, 256>>>(w45f, wth + WOFF_5, 768, 768, 384);             // 7
    hgemm<2><<<dim3(3, NPTS / 128), 128, HG_SMEM>>>(acth + HOFF_H3, wth + WOFF_5, b45p, nullptr, hw2, 768, 384); // 8
    offsets_kernel<<<1, 128>>>(bids);                                                          // 9

    topk1_kernel<<<NBATCH, 1024>>>();
    gath0c_kernel<<<CTOT, 96>>>();

    // pass 2: exact fp32 chain on candidates (validated 128x128 tiles; full L4+L5)
    sgemm_bias_kernel<true ><<<dim3(256 / BN, CTOT / BM), 256>>>(c0,  mw1, mb1, c1,  CTOT,  96, 256);
    sgemm_bias_kernel<true ><<<dim3(512 / BN, CTOT / BM), 256>>>(c1,  mw2, mb2, c2,  CTOT, 256, 512);
    sgemm_bias_kernel<true ><<<dim3(768 / BN, CTOT / BM), 256>>>(c2,  mw3, mb3, c3,  CTOT, 512, 768);
    sgemm_bias_kernel<false><<<dim3(768 / BN, CTOT / BM), 256>>>(c3,  mw4, mb4, cpf, CTOT, 768, 768);
    sgemm_bias_kernel<true ><<<dim3(384 / BN, CTOT / BM), 256>>>(cpf, hw1, hb1, cg,  CTOT, 768, 384);
    cscore_kernel<<<(CTOT * 32 + 255) / 256, 256>>>(hw2, hb2);

    topk2_kernel<<<NBATCH, 256>>>();
    gather_kernel<<<NBATCH * MAX_TOKENS, 192>>>(coords, times, out);
}